// round 11
// baseline (speedup 1.0000x reference)
#include <cuda_runtime.h>
#include <cuda_bf16.h>
#include <math.h>
#include <stdint.h>

#define D_MODEL   1024
#define D_STATE   16
#define D_CONV    4
#define HEADDIM   64
#define CHUNK     64
#define D_INNER   2048
#define NHEADS    32
#define CONV_DIM  2080          // D_INNER + 2*D_STATE
#define D_IN_PROJ 4160          // 2*D_INNER + 2*D_STATE + NHEADS
#define BATCH     2
#define SEQ       4096
#define NCHUNK    (SEQ / CHUNK) // 64
#define MTOT      (BATCH * SEQ) // 8192

// ---------------- scratch (device globals; no allocation allowed) -----------
__device__ float g_zxbcdt[(size_t)MTOT * D_IN_PROJ];
__device__ float g_xBC[(size_t)MTOT * CONV_DIM];
__device__ float g_dt[(size_t)MTOT * NHEADS];
__device__ float g_Acum[(size_t)BATCH * NCHUNK * NHEADS * CHUNK];
__device__ float g_cs[(size_t)BATCH * NCHUNK * NHEADS * HEADDIM * D_STATE];
__device__ float g_sp[(size_t)BATCH * NCHUNK * NHEADS * HEADDIM * D_STATE];
__device__ float g_y[(size_t)MTOT * D_INNER];

// bf16 hi/lo split buffers
__device__ unsigned short g_uhi[(size_t)MTOT * D_MODEL];
__device__ unsigned short g_ulo[(size_t)MTOT * D_MODEL];
__device__ unsigned short g_w1hi[(size_t)D_IN_PROJ * D_MODEL];
__device__ unsigned short g_w1lo[(size_t)D_IN_PROJ * D_MODEL];
__device__ unsigned short g_yhi[(size_t)MTOT * D_INNER];
__device__ unsigned short g_ylo[(size_t)MTOT * D_INNER];
__device__ unsigned short g_w2hi[(size_t)D_MODEL * D_INNER];
__device__ unsigned short g_w2lo[(size_t)D_MODEL * D_INNER];

// ============================================================================
// helpers
// ============================================================================
__device__ __forceinline__ uint32_t cvta_s(const void* p) {
    uint32_t a;
    asm("{ .reg .u64 t; cvta.to.shared.u64 t, %1; cvt.u32.u64 %0, t; }" : "=r"(a) : "l"(p));
    return a;
}
__device__ __forceinline__ void cpa16(uint32_t dst, const void* src, int sz) {
    asm volatile("cp.async.cg.shared.global [%0], [%1], 16, %2;"
                 :: "r"(dst), "l"(src), "r"(sz));
}
#define CP_COMMIT() asm volatile("cp.async.commit_group;" ::: "memory")
#define CP_WAIT1()  asm volatile("cp.async.wait_group 1;" ::: "memory")

__device__ __forceinline__ void ldm_x4(uint32_t& r0, uint32_t& r1, uint32_t& r2,
                                       uint32_t& r3, uint32_t addr) {
    asm volatile("ldmatrix.sync.aligned.m8n8.x4.shared.b16 {%0,%1,%2,%3}, [%4];"
                 : "=r"(r0), "=r"(r1), "=r"(r2), "=r"(r3) : "r"(addr));
}
__device__ __forceinline__ void mma_bf16(float* d, const uint32_t* a, const uint32_t* b) {
    asm volatile(
        "mma.sync.aligned.m16n8k16.row.col.f32.bf16.bf16.f32 "
        "{%0,%1,%2,%3},{%4,%5,%6,%7},{%8,%9},{%0,%1,%2,%3};"
        : "+f"(d[0]), "+f"(d[1]), "+f"(d[2]), "+f"(d[3])
        : "r"(a[0]), "r"(a[1]), "r"(a[2]), "r"(a[3]), "r"(b[0]), "r"(b[1]));
}

// ============================================================================
// bf16 3-term split GEMM: C[M,N] = A[M,K] @ B[N,K]^T (fp32 accuracy ~1e-5)
// Terms along K: [Ahi*Bhi | Ahi*Blo | Alo*Bhi]. CTA tile 128x128, BK=64,
// 128 threads (4 warps 2x2), warp tile 64x64, 3-stage cp.async pipeline,
// 2 CTAs/SM. Fragment-rotation: B fragments loaded per ks, A rotated through
// a 2-deep buffer so LDSM for mi+1 overlaps the MMAs of mi.
// ============================================================================
#define BM 128
#define BN 128
#define BKG 64
#define STG 3
#define NTHR 128
#define ATILE (BM * BKG * 2)       // 16384 B
#define BTILE (BN * BKG * 2)       // 16384 B
#define STGB (ATILE + BTILE)       // 32768 B
#define GSMEM (STG * STGB)         // 98304 B

__global__ __launch_bounds__(NTHR, 2) void bf16gemm3(
    const unsigned short* __restrict__ Ahi, const unsigned short* __restrict__ Alo,
    const unsigned short* __restrict__ Bhi, const unsigned short* __restrict__ Blo,
    float* __restrict__ C, int M, int N, int K)
{
    extern __shared__ char smraw[];
    const uint32_t smb = cvta_s(smraw);
    const int tid = threadIdx.x, lane = tid & 31, wid = tid >> 5;
    const int wm = (wid & 1) * 64, wn = (wid >> 1) * 64;
    const int qr = lane >> 2, qc = lane & 3;
    const int brow = blockIdx.y * BM, bcol = blockIdx.x * BN;
    const int KBblk = K >> 6, KBt = 3 * KBblk;

    float acc[4][8][4];
    #pragma unroll
    for (int mi = 0; mi < 4; mi++)
        #pragma unroll
        for (int ni = 0; ni < 8; ni++)
            #pragma unroll
            for (int r = 0; r < 4; r++) acc[mi][ni][r] = 0.f;

    auto srcsel = [&](int kb, const unsigned short*& pa, const unsigned short*& pb, int& kk) {
        if (kb < KBblk)          { pa = Ahi; pb = Bhi; kk = kb; }
        else if (kb < 2 * KBblk) { pa = Ahi; pb = Blo; kk = kb - KBblk; }
        else                     { pa = Alo; pb = Bhi; kk = kb - 2 * KBblk; }
    };
    auto issueA = [&](int kb) {
        if (kb >= KBt) return;
        const unsigned short *pa, *pb; int kk;
        srcsel(kb, pa, pb, kk);
        const uint32_t abase = smb + (kb % STG) * STGB;
        #pragma unroll
        for (int p = 0; p < 8; p++) {
            int g = tid + p * NTHR;
            int r = g >> 3, cg = g & 7;
            cpa16(abase + r * 128 + ((cg ^ (r & 7)) * 16),
                  pa + (size_t)(brow + r) * K + kk * BKG + cg * 8, 16);
        }
    };
    auto issueB = [&](int kb) {
        if (kb >= KBt) return;
        const unsigned short *pa, *pb; int kk;
        srcsel(kb, pa, pb, kk);
        const uint32_t bbase = smb + (kb % STG) * STGB + ATILE;
        #pragma unroll
        for (int p = 0; p < 8; p++) {
            int g = tid + p * NTHR;
            int r = g >> 3, cg = g & 7;
            int bn = bcol + r;
            cpa16(bbase + r * 128 + ((cg ^ (r & 7)) * 16),
                  pb + (size_t)(bn < N ? bn : 0) * K + kk * BKG + cg * 8,
                  bn < N ? 16 : 0);
        }
    };

    issueA(0); issueB(0); CP_COMMIT();
    issueA(1); issueB(1); CP_COMMIT();

    for (int kb = 0; kb < KBt; kb++) {
        CP_WAIT1();
        __syncthreads();

        const int st = kb % STG;
        const uint32_t abase = smb + st * STGB;
        const uint32_t bbase = abase + ATILE;

        auto ldA = [&](uint32_t* dst, int mi, int ks) {
            int r = wm + mi * 16 + (lane & 15);
            int g = (ks * 2 + (lane >> 4)) ^ (r & 7);
            ldm_x4(dst[0], dst[1], dst[2], dst[3], abase + r * 128 + g * 16);
        };

        #pragma unroll
        for (int ks = 0; ks < 4; ks++) {
            uint32_t bfr[8][2];
            #pragma unroll
            for (int pi = 0; pi < 4; pi++) {
                int r = wn + pi * 16 + (lane & 7) + (((lane >> 4) & 1) << 3);
                int g = (ks * 2 + ((lane >> 3) & 1)) ^ (r & 7);
                ldm_x4(bfr[pi * 2][0], bfr[pi * 2][1],
                       bfr[pi * 2 + 1][0], bfr[pi * 2 + 1][1],
                       bbase + r * 128 + g * 16);
            }
            if (ks == 0) issueA(kb + 2);
            if (ks == 1) issueB(kb + 2);

            uint32_t afb[2][4];
            ldA(afb[0], 0, ks);
            #pragma unroll
            for (int mi = 0; mi < 4; mi++) {
                if (mi < 3) ldA(afb[(mi + 1) & 1], mi + 1, ks);
                #pragma unroll
                for (int ni = 0; ni < 8; ni++)
                    mma_bf16(acc[mi][ni], afb[mi & 1], bfr[ni]);
            }
        }
        CP_COMMIT();
    }

    // epilogue
    #pragma unroll
    for (int mi = 0; mi < 4; mi++) {
        int row0 = brow + wm + mi * 16 + qr;
        #pragma unroll
        for (int ni = 0; ni < 8; ni++) {
            int col = bcol + wn + ni * 8 + qc * 2;
            if (col < N) {
                *(float2*)(C + (size_t)row0 * N + col) =
                    make_float2(acc[mi][ni][0], acc[mi][ni][1]);
                *(float2*)(C + (size_t)(row0 + 8) * N + col) =
                    make_float2(acc[mi][ni][2], acc[mi][ni][3]);
            }
        }
    }
}

// ---------------- fp32 -> bf16 hi/lo split ----------------------------------
__global__ void split_kernel(const float* __restrict__ s,
                             unsigned short* __restrict__ hi,
                             unsigned short* __restrict__ lo, int n)
{
    int i = (blockIdx.x * 256 + threadIdx.x) * 4;
    if (i >= n) return;
    float4 v = *(const float4*)(s + i);
    __nv_bfloat16 h0 = __float2bfloat16_rn(v.x);
    __nv_bfloat16 h1 = __float2bfloat16_rn(v.y);
    __nv_bfloat16 h2 = __float2bfloat16_rn(v.z);
    __nv_bfloat16 h3 = __float2bfloat16_rn(v.w);
    __nv_bfloat16 l0 = __float2bfloat16_rn(v.x - __bfloat162float(h0));
    __nv_bfloat16 l1 = __float2bfloat16_rn(v.y - __bfloat162float(h1));
    __nv_bfloat16 l2 = __float2bfloat16_rn(v.z - __bfloat162float(h2));
    __nv_bfloat16 l3 = __float2bfloat16_rn(v.w - __bfloat162float(h3));
    *(ushort4*)(hi + i) = make_ushort4(*(unsigned short*)&h0, *(unsigned short*)&h1,
                                       *(unsigned short*)&h2, *(unsigned short*)&h3);
    *(ushort4*)(lo + i) = make_ushort4(*(unsigned short*)&l0, *(unsigned short*)&l1,
                                       *(unsigned short*)&l2, *(unsigned short*)&l3);
}

// ---------------- depthwise causal conv(4) + bias + SiLU, fused dt ----------
__global__ void conv_silu_dt_kernel(const float* __restrict__ conv_w,
                                    const float* __restrict__ conv_b,
                                    const float* __restrict__ dt_bias)
{
    int idx = blockIdx.x * blockDim.x + threadIdx.x;

    // fused dt = softplus(raw + bias) on the first MTOT*NHEADS threads
    if (idx < MTOT * NHEADS) {
        int h = idx & (NHEADS - 1);
        int m = idx >> 5;
        float x = g_zxbcdt[(size_t)m * D_IN_PROJ + (D_IN_PROJ - NHEADS) + h] + dt_bias[h];
        g_dt[idx] = (x > 20.f) ? x : log1pf(expf(x));
    }

    if (idx >= MTOT * CONV_DIM) return;
    int c = idx % CONV_DIM;
    int m = idx / CONV_DIM;
    int l = m & (SEQ - 1);

    float acc = conv_b[c];
    #pragma unroll
    for (int j = 0; j < D_CONV; j++) {
        int lj = l - (D_CONV - 1) + j;
        if (lj >= 0)
            acc += conv_w[c * D_CONV + j] *
                   g_zxbcdt[(size_t)(m - (D_CONV - 1) + j) * D_IN_PROJ + D_INNER + c];
    }
    g_xBC[idx] = acc / (1.f + expf(-acc));
}

// ---------------- SSD stage 1: per-chunk diag output + chunk states ---------
__global__ __launch_bounds__(256) void ssd_chunk_kernel(const float* __restrict__ A_log)
{
    __shared__ float xs[CHUNK][HEADDIM];
    __shared__ float Gs[CHUNK][CHUNK];
    __shared__ float Bsh[CHUNK][D_STATE];
    __shared__ float Csh[CHUNK][D_STATE];
    __shared__ float Acum[CHUNK];
    __shared__ float dts[CHUNK];
    __shared__ float decay[CHUNK];
    __shared__ float r4[CHUNK];          // r4[l] = exp(Acum[l+4]-Acum[l])

    const int c = blockIdx.x, h = blockIdx.y, b = blockIdx.z;
    const int t = threadIdx.x;
    const int m0 = b * SEQ + c * CHUNK;

    if (t < CHUNK) dts[t] = g_dt[(size_t)(m0 + t) * NHEADS + h];
    #pragma unroll
    for (int i = 0; i < 4; i++) {
        int idx = t + i * 256;
        int s = idx >> 4, n = idx & 15;
        Bsh[s][n] = g_xBC[(size_t)(m0 + s) * CONV_DIM + D_INNER + n];
        Csh[s][n] = g_xBC[(size_t)(m0 + s) * CONV_DIM + D_INNER + D_STATE + n];
    }
    __syncthreads();
    #pragma unroll
    for (int i = 0; i < 16; i++) {
        int idx = t + i * 256;
        int s = idx >> 6, p = idx & 63;
        xs[s][p] = g_xBC[(size_t)(m0 + s) * CONV_DIM + h * HEADDIM + p] * dts[s];
    }
    __syncthreads();

    if (t == 0) {
        float Ah = -expf(A_log[h]);
        float run = 0.f;
        for (int s = 0; s < CHUNK; s++) { run += Ah * dts[s]; Acum[s] = run; }
    }
    __syncthreads();
    float Alast = Acum[CHUNK - 1];
    if (t < CHUNK) {
        decay[t] = expf(Alast - Acum[t]);
        g_Acum[(((size_t)(b * NCHUNK) + c) * NHEADS + h) * CHUNK + t] = Acum[t];
        r4[t] = (t < CHUNK - 4) ? expf(Acum[t + 4] - Acum[t]) : 0.f;
    }
    __syncthreads();

    // G[l][s] = (C[l]·B[s]) * exp(Acum[l]-Acum[s]), s <= l; exp via recurrence
    {
        const int s = t & 63;
        const int l0 = t >> 6;
        float4 Bq0 = *(const float4*)&Bsh[s][0];
        float4 Bq1 = *(const float4*)&Bsh[s][4];
        float4 Bq2 = *(const float4*)&Bsh[s][8];
        float4 Bq3 = *(const float4*)&Bsh[s][12];
        float As = Acum[s];
        float e = -1.f;
        #pragma unroll
        for (int i = 0; i < 16; i++) {
            int l = l0 + 4 * i;
            float g = 0.f;
            if (l >= s) {
                if (e < 0.f) e = expf(Acum[l] - As);
                else         e *= r4[l - 4];
                float4 c0 = *(const float4*)&Csh[l][0];
                float4 c1 = *(const float4*)&Csh[l][4];
                float4 c2 = *(const float4*)&Csh[l][8];
                float4 c3 = *(const float4*)&Csh[l][12];
                float d = c0.x * Bq0.x + c0.y * Bq0.y + c0.z * Bq0.z + c0.w * Bq0.w
                        + c1.x * Bq1.x + c1.y * Bq1.y + c1.z * Bq1.z + c1.w * Bq1.w
                        + c2.x * Bq2.x + c2.y * Bq2.y + c2.z * Bq2.z + c2.w * Bq2.w
                        + c3.x * Bq3.x + c3.y * Bq3.y + c3.z * Bq3.z + c3.w * Bq3.w;
                g = d * e;
            }
            Gs[l][s] = g;
        }
    }
    __syncthreads();

    // Y_diag = G @ x, s-unrolled by 4, all-float4 shared reads
    {
        const int p0 = (t & 15) * 4;
        const int l0 = (t >> 4) * 4;
        float acc[4][4];
        #pragma unroll
        for (int i = 0; i < 4; i++)
            #pragma unroll
            for (int j = 0; j < 4; j++) acc[i][j] = 0.f;
        for (int s0 = 0; s0 < CHUNK; s0 += 4) {
            float4 xq[4];
            #pragma unroll
            for (int j = 0; j < 4; j++) xq[j] = *(const float4*)&xs[s0 + j][p0];
            #pragma unroll
            for (int i = 0; i < 4; i++) {
                float4 gq = *(const float4*)&Gs[l0 + i][s0];
                acc[i][0] += gq.x * xq[0].x + gq.y * xq[1].x + gq.z * xq[2].x + gq.w * xq[3].x;
                acc[i][1] += gq.x * xq[0].y + gq.y * xq[1].y + gq.z * xq[2].y + gq.w * xq[3].y;
                acc[i][2] += gq.x * xq[0].z + gq.y * xq[1].z + gq.z * xq[2].z + gq.w * xq[3].z;
                acc[i][3] += gq.x * xq[0].w + gq.y * xq[1].w + gq.z * xq[2].w + gq.w * xq[3].w;
            }
        }
        #pragma unroll
        for (int i = 0; i < 4; i++)
            *(float4*)&g_y[(size_t)(m0 + l0 + i) * D_INNER + h * HEADDIM + p0] =
                make_float4(acc[i][0], acc[i][1], acc[i][2], acc[i][3]);
    }

    {
        const int p  = t & 63;
        const int nb = (t >> 6) * 4;
        float acc[4] = {0.f, 0.f, 0.f, 0.f};
        for (int s = 0; s < CHUNK; s++) {
            float xv = xs[s][p] * decay[s];
            #pragma unroll
            for (int j = 0; j < 4; j++) acc[j] += Bsh[s][nb + j] * xv;
        }
        size_t base = ((((size_t)(b * NCHUNK) + c) * NHEADS + h) * HEADDIM + p) * D_STATE + nb;
        #pragma unroll
        for (int j = 0; j < 4; j++) g_cs[base + j] = acc[j];
    }
}

// ---------------- SSD stage 2: sequential cross-chunk state scan ------------
__global__ __launch_bounds__(1024) void ssd_scan_kernel()
{
    const int bh = blockIdx.x;
    const int b = bh / NHEADS, h = bh % NHEADS;
    const int t = threadIdx.x;
    float state = 0.f;
    for (int c = 0; c < NCHUNK; c++) {
        size_t base = (((size_t)(b * NCHUNK) + c) * NHEADS + h) * (HEADDIM * D_STATE);
        g_sp[base + t] = state;
        float dA = expf(g_Acum[(((size_t)(b * NCHUNK) + c) * NHEADS + h) * CHUNK + (CHUNK - 1)]);
        state = state * dA + g_cs[base + t];
    }
}

// ---------------- SSD stage 3: off-diag + D*x + gate(silu(z)) ---------------
__global__ __launch_bounds__(256) void ssd_offdiag_kernel(const float* __restrict__ Dp)
{
    __shared__ float sp[CHUNK][D_STATE];
    __shared__ float Csh[CHUNK][D_STATE];
    __shared__ float eA[CHUNK];

    const int c = blockIdx.x, h = blockIdx.y, b = blockIdx.z;
    const int t = threadIdx.x;
    const int m0 = b * SEQ + c * CHUNK;
    size_t spbase = (((size_t)(b * NCHUNK) + c) * NHEADS + h) * (HEADDIM * D_STATE);

    #pragma unroll
    for (int i = 0; i < 4; i++) {
        int idx = t + i * 256;
        ((float*)sp)[idx] = g_sp[spbase + idx];
        int s = idx >> 4, n = idx & 15;
        Csh[s][n] = g_xBC[(size_t)(m0 + s) * CONV_DIM + D_INNER + D_STATE + n];
    }
    if (t < CHUNK)
        eA[t] = expf(g_Acum[(((size_t)(b * NCHUNK) + c) * NHEADS + h) * CHUNK + t]);
    __syncthreads();

    const float Dh = Dp[h];
    const int p = t & 63;
    const int lbase = (t >> 6) * 16;

    float spr[D_STATE];
    #pragma unroll
    for (int n = 0; n < D_STATE; n++) spr[n] = sp[p][n];

    for (int i = 0; i < 16; i++) {
        int l = lbase + i;
        int m = m0 + l;
        float d = 0.f;
        #pragma unroll
        for (int n = 0; n < D_STATE; n++) d += Csh[l][n] * spr[n];
        size_t yi = (size_t)m * D_INNER + h * HEADDIM + p;
        float yv = g_y[yi] + eA[l] * d;
        yv += Dh * g_xBC[(size_t)m * CONV_DIM + h * HEADDIM + p];
        float z = g_zxbcdt[(size_t)m * D_IN_PROJ + h * HEADDIM + p];
        yv *= z / (1.f + expf(-z));
        g_y[yi] = yv;
    }
}

// ---------------- RMSNorm over D_INNER + bf16 hi/lo split output ------------
__global__ __launch_bounds__(256) void rmsnorm_split_kernel(const float* __restrict__ norm_w)
{
    const int m = blockIdx.x;
    const int t = threadIdx.x;
    size_t base = (size_t)m * D_INNER;
    float s = 0.f;
    for (int i = t; i < D_INNER; i += 256) {
        float v = g_y[base + i];
        s += v * v;
    }
    __shared__ float red[256];
    red[t] = s; __syncthreads();
    for (int o = 128; o > 0; o >>= 1) {
        if (t < o) red[t] += red[t + o];
        __syncthreads();
    }
    float scale = rsqrtf(red[0] / (float)D_INNER + 1e-5f);
    for (int i = t; i < D_INNER; i += 256) {
        float v = g_y[base + i] * scale * norm_w[i];
        __nv_bfloat16 h = __float2bfloat16_rn(v);
        __nv_bfloat16 l = __float2bfloat16_rn(v - __bfloat162float(h));
        g_yhi[base + i] = *(unsigned short*)&h;
        g_ylo[base + i] = *(unsigned short*)&l;
    }
}

// ---------------- launch ----------------------------------------------------
extern "C" void kernel_launch(void* const* d_in, const int* in_sizes, int n_in,
                              void* d_out, int out_size)
{
    const float* u       = (const float*)d_in[0];
    const float* W_in    = (const float*)d_in[1];
    const float* conv_w  = (const float*)d_in[2];
    const float* conv_b  = (const float*)d_in[3];
    const float* dt_bias = (const float*)d_in[4];
    const float* A_log   = (const float*)d_in[5];
    const float* Dp      = (const float*)d_in[6];
    const float* norm_w  = (const float*)d_in[7];
    const float* W_out   = (const float*)d_in[8];
    float* out = (float*)d_out;

    float* zx;
    unsigned short *uhi, *ulo, *w1hi, *w1lo, *yhi, *ylo, *w2hi, *w2lo;
    cudaGetSymbolAddress((void**)&zx, g_zxbcdt);
    cudaGetSymbolAddress((void**)&uhi, g_uhi);
    cudaGetSymbolAddress((void**)&ulo, g_ulo);
    cudaGetSymbolAddress((void**)&w1hi, g_w1hi);
    cudaGetSymbolAddress((void**)&w1lo, g_w1lo);
    cudaGetSymbolAddress((void**)&yhi, g_yhi);
    cudaGetSymbolAddress((void**)&ylo, g_ylo);
    cudaGetSymbolAddress((void**)&w2hi, g_w2hi);
    cudaGetSymbolAddress((void**)&w2lo, g_w2lo);

    cudaFuncSetAttribute(bf16gemm3, cudaFuncAttributeMaxDynamicSharedMemorySize, GSMEM);

    // 0. split inputs to bf16 hi/lo
    split_kernel<<<(MTOT * D_MODEL) / 1024, 256>>>(u, uhi, ulo, MTOT * D_MODEL);
    split_kernel<<<(D_IN_PROJ * D_MODEL) / 1024, 256>>>(W_in, w1hi, w1lo, D_IN_PROJ * D_MODEL);
    split_kernel<<<(D_MODEL * D_INNER) / 1024, 256>>>(W_out, w2hi, w2lo, D_MODEL * D_INNER);

    // 1. in_proj:  zxbcdt = u @ W_in^T   (8192 x 4160 x 1024)
    bf16gemm3<<<dim3((D_IN_PROJ + BN - 1) / BN, MTOT / BM), NTHR, GSMEM>>>(
        uhi, ulo, w1hi, w1lo, zx, MTOT, D_IN_PROJ, D_MODEL);

    // 2. depthwise conv + silu on xBC slice, fused dt = softplus(raw + bias)
    conv_silu_dt_kernel<<<(MTOT * CONV_DIM + 255) / 256, 256>>>(conv_w, conv_b, dt_bias);

    // 3. SSD intra-chunk (Y_diag + chunk states)
    ssd_chunk_kernel<<<dim3(NCHUNK, NHEADS, BATCH), 256>>>(A_log);

    // 4. sequential cross-chunk scan
    ssd_scan_kernel<<<BATCH * NHEADS, 1024>>>();

    // 5. off-diagonal contribution + D*x + gating
    ssd_offdiag_kernel<<<dim3(NCHUNK, NHEADS, BATCH), 256>>>(Dp);

    // 6. RMSNorm (+ bf16 split of y for out_proj)
    rmsnorm_split_kernel<<<MTOT, 256>>>(norm_w);

    // 7. out_proj: out = y @ W_out^T   (8192 x 1024 x 2048)
    bf16gemm3<<<dim3(D_MODEL / BN, MTOT / BM), NTHR, GSMEM>>>(
        yhi, ylo, w2hi, w2lo, out, MTOT, D_MODEL, D_INNER);
}

// round 12
// speedup vs baseline: 1.3021x; 1.3021x over previous
#include <cuda_runtime.h>
#include <cuda_bf16.h>
#include <cuda_fp16.h>
#include <math.h>
#include <stdint.h>

#define D_MODEL   1024
#define D_STATE   16
#define D_CONV    4
#define HEADDIM   64
#define CHUNK     64
#define D_INNER   2048
#define NHEADS    32
#define CONV_DIM  2080          // D_INNER + 2*D_STATE
#define D_IN_PROJ 4160          // 2*D_INNER + 2*D_STATE + NHEADS
#define BATCH     2
#define SEQ       4096
#define NCHUNK    (SEQ / CHUNK) // 64
#define MTOT      (BATCH * SEQ) // 8192

// ---------------- scratch (device globals; no allocation allowed) -----------
__device__ float g_zxbcdt[(size_t)MTOT * D_IN_PROJ];
__device__ float g_xBC[(size_t)MTOT * CONV_DIM];
__device__ float g_dt[(size_t)MTOT * NHEADS];
__device__ float g_Acum[(size_t)BATCH * NCHUNK * NHEADS * CHUNK];
__device__ float g_cs[(size_t)BATCH * NCHUNK * NHEADS * HEADDIM * D_STATE];
__device__ float g_sp[(size_t)BATCH * NCHUNK * NHEADS * HEADDIM * D_STATE];
__device__ float g_y[(size_t)MTOT * D_INNER];

// fp16 split buffers: activations hi/lo, weights hi only
__device__ unsigned short g_uhi[(size_t)MTOT * D_MODEL];
__device__ unsigned short g_ulo[(size_t)MTOT * D_MODEL];
__device__ unsigned short g_w1hi[(size_t)D_IN_PROJ * D_MODEL];
__device__ unsigned short g_yhi[(size_t)MTOT * D_INNER];
__device__ unsigned short g_ylo[(size_t)MTOT * D_INNER];
__device__ unsigned short g_w2hi[(size_t)D_MODEL * D_INNER];

// ============================================================================
// helpers
// ============================================================================
__device__ __forceinline__ uint32_t cvta_s(const void* p) {
    uint32_t a;
    asm("{ .reg .u64 t; cvta.to.shared.u64 t, %1; cvt.u32.u64 %0, t; }" : "=r"(a) : "l"(p));
    return a;
}
__device__ __forceinline__ void cpa16(uint32_t dst, const void* src, int sz) {
    asm volatile("cp.async.cg.shared.global [%0], [%1], 16, %2;"
                 :: "r"(dst), "l"(src), "r"(sz));
}
#define CP_COMMIT() asm volatile("cp.async.commit_group;" ::: "memory")
#define CP_WAIT1()  asm volatile("cp.async.wait_group 1;" ::: "memory")

__device__ __forceinline__ void ldm_x4(uint32_t& r0, uint32_t& r1, uint32_t& r2,
                                       uint32_t& r3, uint32_t addr) {
    asm volatile("ldmatrix.sync.aligned.m8n8.x4.shared.b16 {%0,%1,%2,%3}, [%4];"
                 : "=r"(r0), "=r"(r1), "=r"(r2), "=r"(r3) : "r"(addr));
}
__device__ __forceinline__ void mma_f16(float* d, const uint32_t* a, const uint32_t* b) {
    asm volatile(
        "mma.sync.aligned.m16n8k16.row.col.f32.f16.f16.f32 "
        "{%0,%1,%2,%3},{%4,%5,%6,%7},{%8,%9},{%0,%1,%2,%3};"
        : "+f"(d[0]), "+f"(d[1]), "+f"(d[2]), "+f"(d[3])
        : "r"(a[0]), "r"(a[1]), "r"(a[2]), "r"(a[3]), "r"(b[0]), "r"(b[1]));
}

// ============================================================================
// fp16 2-term split GEMM: C[M,N] = A[M,K] @ B[N,K]^T
// A = Ahi + Alo (exact fp16 split of fp32), B = fp16(B).
// Terms along K: [Ahi*Bhi | Alo*Bhi] -> C = A*Bhi exactly (fp32 accum);
// only error is the fp16 rounding of B (~2^-12, incoherent over K).
// CTA tile 128x128, BK=64, 128 threads (4 warps 2x2), warp tile 64x64,
// 3-stage cp.async pipeline, 2 CTAs/SM, cp.async spread across ks loop.
// ============================================================================
#define BM 128
#define BN 128
#define BKG 64
#define STG 3
#define NTHR 128
#define ATILE (BM * BKG * 2)       // 16384 B
#define BTILE (BN * BKG * 2)       // 16384 B
#define STGB (ATILE + BTILE)       // 32768 B
#define GSMEM (STG * STGB)         // 98304 B

__global__ __launch_bounds__(NTHR, 2) void f16gemm2(
    const unsigned short* __restrict__ Ahi, const unsigned short* __restrict__ Alo,
    const unsigned short* __restrict__ Bhi,
    float* __restrict__ C, int M, int N, int K)
{
    extern __shared__ char smraw[];
    const uint32_t smb = cvta_s(smraw);
    const int tid = threadIdx.x, lane = tid & 31, wid = tid >> 5;
    const int wm = (wid & 1) * 64, wn = (wid >> 1) * 64;
    const int qr = lane >> 2, qc = lane & 3;
    const int brow = blockIdx.y * BM, bcol = blockIdx.x * BN;
    const int KBblk = K >> 6, KBt = 2 * KBblk;

    float acc[4][8][4];
    #pragma unroll
    for (int mi = 0; mi < 4; mi++)
        #pragma unroll
        for (int ni = 0; ni < 8; ni++)
            #pragma unroll
            for (int r = 0; r < 4; r++) acc[mi][ni][r] = 0.f;

    auto issueA = [&](int kb) {
        if (kb >= KBt) return;
        const unsigned short* pa = (kb < KBblk) ? Ahi : Alo;
        const int kk = (kb < KBblk) ? kb : kb - KBblk;
        const uint32_t abase = smb + (kb % STG) * STGB;
        #pragma unroll
        for (int p = 0; p < 8; p++) {
            int g = tid + p * NTHR;
            int r = g >> 3, cg = g & 7;
            cpa16(abase + r * 128 + ((cg ^ (r & 7)) * 16),
                  pa + (size_t)(brow + r) * K + kk * BKG + cg * 8, 16);
        }
    };
    auto issueB = [&](int kb) {
        if (kb >= KBt) return;
        const int kk = (kb < KBblk) ? kb : kb - KBblk;
        const uint32_t bbase = smb + (kb % STG) * STGB + ATILE;
        #pragma unroll
        for (int p = 0; p < 8; p++) {
            int g = tid + p * NTHR;
            int r = g >> 3, cg = g & 7;
            int bn = bcol + r;
            cpa16(bbase + r * 128 + ((cg ^ (r & 7)) * 16),
                  Bhi + (size_t)(bn < N ? bn : 0) * K + kk * BKG + cg * 8,
                  bn < N ? 16 : 0);
        }
    };

    issueA(0); issueB(0); CP_COMMIT();
    issueA(1); issueB(1); CP_COMMIT();

    for (int kb = 0; kb < KBt; kb++) {
        CP_WAIT1();
        __syncthreads();

        const int st = kb % STG;
        const uint32_t abase = smb + st * STGB;
        const uint32_t bbase = abase + ATILE;
        #pragma unroll
        for (int ks = 0; ks < 4; ks++) {
            uint32_t af[4][4], bfr[8][2];
            #pragma unroll
            for (int mi = 0; mi < 4; mi++) {
                int r = wm + mi * 16 + (lane & 15);
                int g = (ks * 2 + (lane >> 4)) ^ (r & 7);
                ldm_x4(af[mi][0], af[mi][1], af[mi][2], af[mi][3],
                       abase + r * 128 + g * 16);
            }
            #pragma unroll
            for (int pi = 0; pi < 4; pi++) {
                int r = wn + pi * 16 + (lane & 7) + (((lane >> 4) & 1) << 3);
                int g = (ks * 2 + ((lane >> 3) & 1)) ^ (r & 7);
                ldm_x4(bfr[pi * 2][0], bfr[pi * 2][1],
                       bfr[pi * 2 + 1][0], bfr[pi * 2 + 1][1],
                       bbase + r * 128 + g * 16);
            }
            if (ks == 0) issueA(kb + 2);
            if (ks == 1) issueB(kb + 2);
            #pragma unroll
            for (int mi = 0; mi < 4; mi++)
                #pragma unroll
                for (int ni = 0; ni < 8; ni++)
                    mma_f16(acc[mi][ni], af[mi], bfr[ni]);
        }
        CP_COMMIT();
    }

    // epilogue
    #pragma unroll
    for (int mi = 0; mi < 4; mi++) {
        int row0 = brow + wm + mi * 16 + qr;
        #pragma unroll
        for (int ni = 0; ni < 8; ni++) {
            int col = bcol + wn + ni * 8 + qc * 2;
            if (col < N) {
                *(float2*)(C + (size_t)row0 * N + col) =
                    make_float2(acc[mi][ni][0], acc[mi][ni][1]);
                *(float2*)(C + (size_t)(row0 + 8) * N + col) =
                    make_float2(acc[mi][ni][2], acc[mi][ni][3]);
            }
        }
    }
}

// ---------------- fp32 -> fp16 hi/lo split (activations) --------------------
__global__ void split2_kernel(const float* __restrict__ s,
                              unsigned short* __restrict__ hi,
                              unsigned short* __restrict__ lo, int n)
{
    int i = (blockIdx.x * 256 + threadIdx.x) * 4;
    if (i >= n) return;
    float4 v = *(const float4*)(s + i);
    __half h0 = __float2half_rn(v.x);
    __half h1 = __float2half_rn(v.y);
    __half h2 = __float2half_rn(v.z);
    __half h3 = __float2half_rn(v.w);
    __half l0 = __float2half_rn(v.x - __half2float(h0));
    __half l1 = __float2half_rn(v.y - __half2float(h1));
    __half l2 = __float2half_rn(v.z - __half2float(h2));
    __half l3 = __float2half_rn(v.w - __half2float(h3));
    *(ushort4*)(hi + i) = make_ushort4(*(unsigned short*)&h0, *(unsigned short*)&h1,
                                       *(unsigned short*)&h2, *(unsigned short*)&h3);
    *(ushort4*)(lo + i) = make_ushort4(*(unsigned short*)&l0, *(unsigned short*)&l1,
                                       *(unsigned short*)&l2, *(unsigned short*)&l3);
}

// ---------------- fp32 -> fp16 (weights, hi only) ---------------------------
__global__ void split1_kernel(const float* __restrict__ s,
                              unsigned short* __restrict__ hi, int n)
{
    int i = (blockIdx.x * 256 + threadIdx.x) * 4;
    if (i >= n) return;
    float4 v = *(const float4*)(s + i);
    __half h0 = __float2half_rn(v.x);
    __half h1 = __float2half_rn(v.y);
    __half h2 = __float2half_rn(v.z);
    __half h3 = __float2half_rn(v.w);
    *(ushort4*)(hi + i) = make_ushort4(*(unsigned short*)&h0, *(unsigned short*)&h1,
                                       *(unsigned short*)&h2, *(unsigned short*)&h3);
}

// ---------------- depthwise causal conv(4) + bias + SiLU, fused dt ----------
__global__ void conv_silu_dt_kernel(const float* __restrict__ conv_w,
                                    const float* __restrict__ conv_b,
                                    const float* __restrict__ dt_bias)
{
    int idx = blockIdx.x * blockDim.x + threadIdx.x;

    if (idx < MTOT * NHEADS) {
        int h = idx & (NHEADS - 1);
        int m = idx >> 5;
        float x = g_zxbcdt[(size_t)m * D_IN_PROJ + (D_IN_PROJ - NHEADS) + h] + dt_bias[h];
        g_dt[idx] = (x > 20.f) ? x : log1pf(expf(x));
    }

    if (idx >= MTOT * CONV_DIM) return;
    int c = idx % CONV_DIM;
    int m = idx / CONV_DIM;
    int l = m & (SEQ - 1);

    float acc = conv_b[c];
    #pragma unroll
    for (int j = 0; j < D_CONV; j++) {
        int lj = l - (D_CONV - 1) + j;
        if (lj >= 0)
            acc += conv_w[c * D_CONV + j] *
                   g_zxbcdt[(size_t)(m - (D_CONV - 1) + j) * D_IN_PROJ + D_INNER + c];
    }
    g_xBC[idx] = acc / (1.f + expf(-acc));
}

// ---------------- SSD stage 1: per-chunk diag output + chunk states ---------
__global__ __launch_bounds__(256) void ssd_chunk_kernel(const float* __restrict__ A_log)
{
    __shared__ float xs[CHUNK][HEADDIM];
    __shared__ float Gs[CHUNK][CHUNK];
    __shared__ float Bsh[CHUNK][D_STATE];
    __shared__ float Csh[CHUNK][D_STATE];
    __shared__ float Acum[CHUNK];
    __shared__ float dts[CHUNK];
    __shared__ float decay[CHUNK];
    __shared__ float r4[CHUNK];          // r4[l] = exp(Acum[l+4]-Acum[l])

    const int c = blockIdx.x, h = blockIdx.y, b = blockIdx.z;
    const int t = threadIdx.x;
    const int m0 = b * SEQ + c * CHUNK;

    if (t < CHUNK) dts[t] = g_dt[(size_t)(m0 + t) * NHEADS + h];
    #pragma unroll
    for (int i = 0; i < 4; i++) {
        int idx = t + i * 256;
        int s = idx >> 4, n = idx & 15;
        Bsh[s][n] = g_xBC[(size_t)(m0 + s) * CONV_DIM + D_INNER + n];
        Csh[s][n] = g_xBC[(size_t)(m0 + s) * CONV_DIM + D_INNER + D_STATE + n];
    }
    __syncthreads();
    #pragma unroll
    for (int i = 0; i < 16; i++) {
        int idx = t + i * 256;
        int s = idx >> 6, p = idx & 63;
        xs[s][p] = g_xBC[(size_t)(m0 + s) * CONV_DIM + h * HEADDIM + p] * dts[s];
    }
    __syncthreads();

    if (t == 0) {
        float Ah = -expf(A_log[h]);
        float run = 0.f;
        for (int s = 0; s < CHUNK; s++) { run += Ah * dts[s]; Acum[s] = run; }
    }
    __syncthreads();
    float Alast = Acum[CHUNK - 1];
    if (t < CHUNK) {
        decay[t] = expf(Alast - Acum[t]);
        g_Acum[(((size_t)(b * NCHUNK) + c) * NHEADS + h) * CHUNK + t] = Acum[t];
        r4[t] = (t < CHUNK - 4) ? expf(Acum[t + 4] - Acum[t]) : 0.f;
    }
    __syncthreads();

    // G[l][s] = (C[l]·B[s]) * exp(Acum[l]-Acum[s]), s <= l; exp via recurrence
    {
        const int s = t & 63;
        const int l0 = t >> 6;
        float4 Bq0 = *(const float4*)&Bsh[s][0];
        float4 Bq1 = *(const float4*)&Bsh[s][4];
        float4 Bq2 = *(const float4*)&Bsh[s][8];
        float4 Bq3 = *(const float4*)&Bsh[s][12];
        float As = Acum[s];
        float e = -1.f;
        #pragma unroll
        for (int i = 0; i < 16; i++) {
            int l = l0 + 4 * i;
            float g = 0.f;
            if (l >= s) {
                if (e < 0.f) e = expf(Acum[l] - As);
                else         e *= r4[l - 4];
                float4 c0 = *(const float4*)&Csh[l][0];
                float4 c1 = *(const float4*)&Csh[l][4];
                float4 c2 = *(const float4*)&Csh[l][8];
                float4 c3 = *(const float4*)&Csh[l][12];
                float d = c0.x * Bq0.x + c0.y * Bq0.y + c0.z * Bq0.z + c0.w * Bq0.w
                        + c1.x * Bq1.x + c1.y * Bq1.y + c1.z * Bq1.z + c1.w * Bq1.w
                        + c2.x * Bq2.x + c2.y * Bq2.y + c2.z * Bq2.z + c2.w * Bq2.w
                        + c3.x * Bq3.x + c3.y * Bq3.y + c3.z * Bq3.z + c3.w * Bq3.w;
                g = d * e;
            }
            Gs[l][s] = g;
        }
    }
    __syncthreads();

    // Y_diag = G @ x, s-unrolled by 4, all-float4 shared reads
    {
        const int p0 = (t & 15) * 4;
        const int l0 = (t >> 4) * 4;
        float acc[4][4];
        #pragma unroll
        for (int i = 0; i < 4; i++)
            #pragma unroll
            for (int j = 0; j < 4; j++) acc[i][j] = 0.f;
        for (int s0 = 0; s0 < CHUNK; s0 += 4) {
            float4 xq[4];
            #pragma unroll
            for (int j = 0; j < 4; j++) xq[j] = *(const float4*)&xs[s0 + j][p0];
            #pragma unroll
            for (int i = 0; i < 4; i++) {
                float4 gq = *(const float4*)&Gs[l0 + i][s0];
                acc[i][0] += gq.x * xq[0].x + gq.y * xq[1].x + gq.z * xq[2].x + gq.w * xq[3].x;
                acc[i][1] += gq.x * xq[0].y + gq.y * xq[1].y + gq.z * xq[2].y + gq.w * xq[3].y;
                acc[i][2] += gq.x * xq[0].z + gq.y * xq[1].z + gq.z * xq[2].z + gq.w * xq[3].z;
                acc[i][3] += gq.x * xq[0].w + gq.y * xq[1].w + gq.z * xq[2].w + gq.w * xq[3].w;
            }
        }
        #pragma unroll
        for (int i = 0; i < 4; i++)
            *(float4*)&g_y[(size_t)(m0 + l0 + i) * D_INNER + h * HEADDIM + p0] =
                make_float4(acc[i][0], acc[i][1], acc[i][2], acc[i][3]);
    }

    {
        const int p  = t & 63;
        const int nb = (t >> 6) * 4;
        float acc[4] = {0.f, 0.f, 0.f, 0.f};
        for (int s = 0; s < CHUNK; s++) {
            float xv = xs[s][p] * decay[s];
            #pragma unroll
            for (int j = 0; j < 4; j++) acc[j] += Bsh[s][nb + j] * xv;
        }
        size_t base = ((((size_t)(b * NCHUNK) + c) * NHEADS + h) * HEADDIM + p) * D_STATE + nb;
        #pragma unroll
        for (int j = 0; j < 4; j++) g_cs[base + j] = acc[j];
    }
}

// ---------------- SSD stage 2: sequential cross-chunk state scan ------------
__global__ __launch_bounds__(1024) void ssd_scan_kernel()
{
    const int bh = blockIdx.x;
    const int b = bh / NHEADS, h = bh % NHEADS;
    const int t = threadIdx.x;
    float state = 0.f;
    for (int c = 0; c < NCHUNK; c++) {
        size_t base = (((size_t)(b * NCHUNK) + c) * NHEADS + h) * (HEADDIM * D_STATE);
        g_sp[base + t] = state;
        float dA = expf(g_Acum[(((size_t)(b * NCHUNK) + c) * NHEADS + h) * CHUNK + (CHUNK - 1)]);
        state = state * dA + g_cs[base + t];
    }
}

// ---------------- SSD stage 3: off-diag + D*x + gate(silu(z)) ---------------
__global__ __launch_bounds__(256) void ssd_offdiag_kernel(const float* __restrict__ Dp)
{
    __shared__ float sp[CHUNK][D_STATE];
    __shared__ float Csh[CHUNK][D_STATE];
    __shared__ float eA[CHUNK];

    const int c = blockIdx.x, h = blockIdx.y, b = blockIdx.z;
    const int t = threadIdx.x;
    const int m0 = b * SEQ + c * CHUNK;
    size_t spbase = (((size_t)(b * NCHUNK) + c) * NHEADS + h) * (HEADDIM * D_STATE);

    #pragma unroll
    for (int i = 0; i < 4; i++) {
        int idx = t + i * 256;
        ((float*)sp)[idx] = g_sp[spbase + idx];
        int s = idx >> 4, n = idx & 15;
        Csh[s][n] = g_xBC[(size_t)(m0 + s) * CONV_DIM + D_INNER + D_STATE + n];
    }
    if (t < CHUNK)
        eA[t] = expf(g_Acum[(((size_t)(b * NCHUNK) + c) * NHEADS + h) * CHUNK + t]);
    __syncthreads();

    const float Dh = Dp[h];
    const int p = t & 63;
    const int lbase = (t >> 6) * 16;

    float spr[D_STATE];
    #pragma unroll
    for (int n = 0; n < D_STATE; n++) spr[n] = sp[p][n];

    for (int i = 0; i < 16; i++) {
        int l = lbase + i;
        int m = m0 + l;
        float d = 0.f;
        #pragma unroll
        for (int n = 0; n < D_STATE; n++) d += Csh[l][n] * spr[n];
        size_t yi = (size_t)m * D_INNER + h * HEADDIM + p;
        float yv = g_y[yi] + eA[l] * d;
        yv += Dh * g_xBC[(size_t)m * CONV_DIM + h * HEADDIM + p];
        float z = g_zxbcdt[(size_t)m * D_IN_PROJ + h * HEADDIM + p];
        yv *= z / (1.f + expf(-z));
        g_y[yi] = yv;
    }
}

// ---------------- RMSNorm over D_INNER + fp16 hi/lo split output ------------
__global__ __launch_bounds__(256) void rmsnorm_split_kernel(const float* __restrict__ norm_w)
{
    const int m = blockIdx.x;
    const int t = threadIdx.x;
    size_t base = (size_t)m * D_INNER;
    float s = 0.f;
    for (int i = t; i < D_INNER; i += 256) {
        float v = g_y[base + i];
        s += v * v;
    }
    __shared__ float red[256];
    red[t] = s; __syncthreads();
    for (int o = 128; o > 0; o >>= 1) {
        if (t < o) red[t] += red[t + o];
        __syncthreads();
    }
    float scale = rsqrtf(red[0] / (float)D_INNER + 1e-5f);
    for (int i = t; i < D_INNER; i += 256) {
        float v = g_y[base + i] * scale * norm_w[i];
        __half h = __float2half_rn(v);
        __half l = __float2half_rn(v - __half2float(h));
        g_yhi[base + i] = *(unsigned short*)&h;
        g_ylo[base + i] = *(unsigned short*)&l;
    }
}

// ---------------- launch ----------------------------------------------------
extern "C" void kernel_launch(void* const* d_in, const int* in_sizes, int n_in,
                              void* d_out, int out_size)
{
    const float* u       = (const float*)d_in[0];
    const float* W_in    = (const float*)d_in[1];
    const float* conv_w  = (const float*)d_in[2];
    const float* conv_b  = (const float*)d_in[3];
    const float* dt_bias = (const float*)d_in[4];
    const float* A_log   = (const float*)d_in[5];
    const float* Dp      = (const float*)d_in[6];
    const float* norm_w  = (const float*)d_in[7];
    const float* W_out   = (const float*)d_in[8];
    float* out = (float*)d_out;

    float* zx;
    unsigned short *uhi, *ulo, *w1hi, *yhi, *ylo, *w2hi;
    cudaGetSymbolAddress((void**)&zx, g_zxbcdt);
    cudaGetSymbolAddress((void**)&uhi, g_uhi);
    cudaGetSymbolAddress((void**)&ulo, g_ulo);
    cudaGetSymbolAddress((void**)&w1hi, g_w1hi);
    cudaGetSymbolAddress((void**)&yhi, g_yhi);
    cudaGetSymbolAddress((void**)&ylo, g_ylo);
    cudaGetSymbolAddress((void**)&w2hi, g_w2hi);

    cudaFuncSetAttribute(f16gemm2, cudaFuncAttributeMaxDynamicSharedMemorySize, GSMEM);

    // 0. split inputs: activations -> fp16 hi/lo; weights -> fp16
    split2_kernel<<<(MTOT * D_MODEL) / 1024, 256>>>(u, uhi, ulo, MTOT * D_MODEL);
    split1_kernel<<<(D_IN_PROJ * D_MODEL) / 1024, 256>>>(W_in, w1hi, D_IN_PROJ * D_MODEL);
    split1_kernel<<<(D_MODEL * D_INNER) / 1024, 256>>>(W_out, w2hi, D_MODEL * D_INNER);

    // 1. in_proj:  zxbcdt = u @ W_in^T   (8192 x 4160 x 1024)
    f16gemm2<<<dim3((D_IN_PROJ + BN - 1) / BN, MTOT / BM), NTHR, GSMEM>>>(
        uhi, ulo, w1hi, zx, MTOT, D_IN_PROJ, D_MODEL);

    // 2. depthwise conv + silu on xBC slice, fused dt = softplus(raw + bias)
    conv_silu_dt_kernel<<<(MTOT * CONV_DIM + 255) / 256, 256>>>(conv_w, conv_b, dt_bias);

    // 3. SSD intra-chunk (Y_diag + chunk states)
    ssd_chunk_kernel<<<dim3(NCHUNK, NHEADS, BATCH), 256>>>(A_log);

    // 4. sequential cross-chunk scan
    ssd_scan_kernel<<<BATCH * NHEADS, 1024>>>();

    // 5. off-diagonal contribution + D*x + gating
    ssd_offdiag_kernel<<<dim3(NCHUNK, NHEADS, BATCH), 256>>>(Dp);

    // 6. RMSNorm (+ fp16 split of y for out_proj)
    rmsnorm_split_kernel<<<MTOT, 256>>>(norm_w);

    // 7. out_proj: out = y @ W_out^T   (8192 x 1024 x 2048)
    f16gemm2<<<dim3(D_MODEL / BN, MTOT / BM), NTHR, GSMEM>>>(
        yhi, ylo, w2hi, out, MTOT, D_MODEL, D_INNER);
}

// round 13
// speedup vs baseline: 1.8320x; 1.4070x over previous
#include <cuda_runtime.h>
#include <cuda_bf16.h>
#include <cuda_fp16.h>
#include <math.h>
#include <stdint.h>

#define D_MODEL   1024
#define D_STATE   16
#define D_CONV    4
#define HEADDIM   64
#define CHUNK     64
#define D_INNER   2048
#define NHEADS    32
#define CONV_DIM  2080          // D_INNER + 2*D_STATE
#define D_IN_PROJ 4160          // 2*D_INNER + 2*D_STATE + NHEADS
#define BATCH     2
#define SEQ       4096
#define NCHUNK    (SEQ / CHUNK) // 64
#define MTOT      (BATCH * SEQ) // 8192

// ---------------- scratch (device globals; no allocation allowed) -----------
__device__ float g_zxbcdt[(size_t)MTOT * D_IN_PROJ];
__device__ float g_xBC[(size_t)MTOT * CONV_DIM];
__device__ float g_dt[(size_t)MTOT * NHEADS];
__device__ float g_Acum[(size_t)BATCH * NCHUNK * NHEADS * CHUNK];
__device__ float g_cs[(size_t)BATCH * NCHUNK * NHEADS * HEADDIM * D_STATE];
__device__ float g_sp[(size_t)BATCH * NCHUNK * NHEADS * HEADDIM * D_STATE];
__device__ float g_y[(size_t)MTOT * D_INNER];

// fp16 buffers
__device__ unsigned short g_uh[(size_t)MTOT * D_MODEL];
__device__ unsigned short g_w1h[(size_t)D_IN_PROJ * D_MODEL];
__device__ unsigned short g_yh[(size_t)MTOT * D_INNER];
__device__ unsigned short g_w2h[(size_t)D_MODEL * D_INNER];

// ============================================================================
// helpers
// ============================================================================
__device__ __forceinline__ uint32_t cvta_s(const void* p) {
    uint32_t a;
    asm("{ .reg .u64 t; cvta.to.shared.u64 t, %1; cvt.u32.u64 %0, t; }" : "=r"(a) : "l"(p));
    return a;
}
__device__ __forceinline__ void cpa16(uint32_t dst, const void* src, int sz) {
    asm volatile("cp.async.cg.shared.global [%0], [%1], 16, %2;"
                 :: "r"(dst), "l"(src), "r"(sz));
}
#define CP_COMMIT() asm volatile("cp.async.commit_group;" ::: "memory")
#define CP_WAIT1()  asm volatile("cp.async.wait_group 1;" ::: "memory")

__device__ __forceinline__ void ldm_x4(uint32_t& r0, uint32_t& r1, uint32_t& r2,
                                       uint32_t& r3, uint32_t addr) {
    asm volatile("ldmatrix.sync.aligned.m8n8.x4.shared.b16 {%0,%1,%2,%3}, [%4];"
                 : "=r"(r0), "=r"(r1), "=r"(r2), "=r"(r3) : "r"(addr));
}
__device__ __forceinline__ void mma_f16(float* d, const uint32_t* a, const uint32_t* b) {
    asm volatile(
        "mma.sync.aligned.m16n8k16.row.col.f32.f16.f16.f32 "
        "{%0,%1,%2,%3},{%4,%5,%6,%7},{%8,%9},{%0,%1,%2,%3};"
        : "+f"(d[0]), "+f"(d[1]), "+f"(d[2]), "+f"(d[3])
        : "r"(a[0]), "r"(a[1]), "r"(a[2]), "r"(a[3]), "r"(b[0]), "r"(b[1]));
}

// ============================================================================
// fp16 GEMM (f32 accumulate): C[M,N] = A[M,K] @ B[N,K]^T
// CTA tile 128x128, BK=64, 128 threads (4 warps 2x2), warp tile 64x64,
// 3-stage cp.async pipeline, 2 CTAs/SM, cp.async spread across ks loop.
// ============================================================================
#define BM 128
#define BN 128
#define BKG 64
#define STG 3
#define NTHR 128
#define ATILE (BM * BKG * 2)       // 16384 B
#define BTILE (BN * BKG * 2)       // 16384 B
#define STGB (ATILE + BTILE)       // 32768 B
#define GSMEM (STG * STGB)         // 98304 B

__global__ __launch_bounds__(NTHR, 2) void f16gemm(
    const unsigned short* __restrict__ Ah,
    const unsigned short* __restrict__ Bh,
    float* __restrict__ C, int M, int N, int K)
{
    extern __shared__ char smraw[];
    const uint32_t smb = cvta_s(smraw);
    const int tid = threadIdx.x, lane = tid & 31, wid = tid >> 5;
    const int wm = (wid & 1) * 64, wn = (wid >> 1) * 64;
    const int qr = lane >> 2, qc = lane & 3;
    const int brow = blockIdx.y * BM, bcol = blockIdx.x * BN;
    const int KBt = K >> 6;

    float acc[4][8][4];
    #pragma unroll
    for (int mi = 0; mi < 4; mi++)
        #pragma unroll
        for (int ni = 0; ni < 8; ni++)
            #pragma unroll
            for (int r = 0; r < 4; r++) acc[mi][ni][r] = 0.f;

    auto issueA = [&](int kb) {
        if (kb >= KBt) return;
        const uint32_t abase = smb + (kb % STG) * STGB;
        #pragma unroll
        for (int p = 0; p < 8; p++) {
            int g = tid + p * NTHR;
            int r = g >> 3, cg = g & 7;
            cpa16(abase + r * 128 + ((cg ^ (r & 7)) * 16),
                  Ah + (size_t)(brow + r) * K + kb * BKG + cg * 8, 16);
        }
    };
    auto issueB = [&](int kb) {
        if (kb >= KBt) return;
        const uint32_t bbase = smb + (kb % STG) * STGB + ATILE;
        #pragma unroll
        for (int p = 0; p < 8; p++) {
            int g = tid + p * NTHR;
            int r = g >> 3, cg = g & 7;
            int bn = bcol + r;
            cpa16(bbase + r * 128 + ((cg ^ (r & 7)) * 16),
                  Bh + (size_t)(bn < N ? bn : 0) * K + kb * BKG + cg * 8,
                  bn < N ? 16 : 0);
        }
    };

    issueA(0); issueB(0); CP_COMMIT();
    issueA(1); issueB(1); CP_COMMIT();

    for (int kb = 0; kb < KBt; kb++) {
        CP_WAIT1();
        __syncthreads();

        const int st = kb % STG;
        const uint32_t abase = smb + st * STGB;
        const uint32_t bbase = abase + ATILE;
        #pragma unroll
        for (int ks = 0; ks < 4; ks++) {
            uint32_t af[4][4], bfr[8][2];
            #pragma unroll
            for (int mi = 0; mi < 4; mi++) {
                int r = wm + mi * 16 + (lane & 15);
                int g = (ks * 2 + (lane >> 4)) ^ (r & 7);
                ldm_x4(af[mi][0], af[mi][1], af[mi][2], af[mi][3],
                       abase + r * 128 + g * 16);
            }
            #pragma unroll
            for (int pi = 0; pi < 4; pi++) {
                int r = wn + pi * 16 + (lane & 7) + (((lane >> 4) & 1) << 3);
                int g = (ks * 2 + ((lane >> 3) & 1)) ^ (r & 7);
                ldm_x4(bfr[pi * 2][0], bfr[pi * 2][1],
                       bfr[pi * 2 + 1][0], bfr[pi * 2 + 1][1],
                       bbase + r * 128 + g * 16);
            }
            if (ks == 0) issueA(kb + 2);
            if (ks == 1) issueB(kb + 2);
            #pragma unroll
            for (int mi = 0; mi < 4; mi++)
                #pragma unroll
                for (int ni = 0; ni < 8; ni++)
                    mma_f16(acc[mi][ni], af[mi], bfr[ni]);
        }
        CP_COMMIT();
    }

    // epilogue
    #pragma unroll
    for (int mi = 0; mi < 4; mi++) {
        int row0 = brow + wm + mi * 16 + qr;
        #pragma unroll
        for (int ni = 0; ni < 8; ni++) {
            int col = bcol + wn + ni * 8 + qc * 2;
            if (col < N) {
                *(float2*)(C + (size_t)row0 * N + col) =
                    make_float2(acc[mi][ni][0], acc[mi][ni][1]);
                *(float2*)(C + (size_t)(row0 + 8) * N + col) =
                    make_float2(acc[mi][ni][2], acc[mi][ni][3]);
            }
        }
    }
}

// ---------------- fp32 -> fp16 conversion -----------------------------------
__global__ void cvt16_kernel(const float* __restrict__ s,
                             unsigned short* __restrict__ hi, int n)
{
    int i = (blockIdx.x * 256 + threadIdx.x) * 4;
    if (i >= n) return;
    float4 v = *(const float4*)(s + i);
    __half h0 = __float2half_rn(v.x);
    __half h1 = __float2half_rn(v.y);
    __half h2 = __float2half_rn(v.z);
    __half h3 = __float2half_rn(v.w);
    *(ushort4*)(hi + i) = make_ushort4(*(unsigned short*)&h0, *(unsigned short*)&h1,
                                       *(unsigned short*)&h2, *(unsigned short*)&h3);
}

// ---------------- depthwise causal conv(4) + bias + SiLU, fused dt ----------
__global__ void conv_silu_dt_kernel(const float* __restrict__ conv_w,
                                    const float* __restrict__ conv_b,
                                    const float* __restrict__ dt_bias)
{
    int idx = blockIdx.x * blockDim.x + threadIdx.x;

    if (idx < MTOT * NHEADS) {
        int h = idx & (NHEADS - 1);
        int m = idx >> 5;
        float x = g_zxbcdt[(size_t)m * D_IN_PROJ + (D_IN_PROJ - NHEADS) + h] + dt_bias[h];
        g_dt[idx] = (x > 20.f) ? x : log1pf(expf(x));
    }

    if (idx >= MTOT * CONV_DIM) return;
    int c = idx % CONV_DIM;
    int m = idx / CONV_DIM;
    int l = m & (SEQ - 1);

    float acc = conv_b[c];
    #pragma unroll
    for (int j = 0; j < D_CONV; j++) {
        int lj = l - (D_CONV - 1) + j;
        if (lj >= 0)
            acc += conv_w[c * D_CONV + j] *
                   g_zxbcdt[(size_t)(m - (D_CONV - 1) + j) * D_IN_PROJ + D_INNER + c];
    }
    g_xBC[idx] = acc / (1.f + expf(-acc));
}

// ---------------- SSD stage 1: per-chunk diag output + chunk states ---------
__global__ __launch_bounds__(256) void ssd_chunk_kernel(const float* __restrict__ A_log)
{
    __shared__ float xs[CHUNK][HEADDIM];
    __shared__ float Gs[CHUNK][CHUNK];
    __shared__ float Bsh[CHUNK][D_STATE];
    __shared__ float Csh[CHUNK][D_STATE];
    __shared__ float Acum[CHUNK];
    __shared__ float dts[CHUNK];
    __shared__ float decay[CHUNK];
    __shared__ float r4[CHUNK];          // r4[l] = exp(Acum[l+4]-Acum[l])

    const int c = blockIdx.x, h = blockIdx.y, b = blockIdx.z;
    const int t = threadIdx.x;
    const int m0 = b * SEQ + c * CHUNK;

    if (t < CHUNK) dts[t] = g_dt[(size_t)(m0 + t) * NHEADS + h];
    #pragma unroll
    for (int i = 0; i < 4; i++) {
        int idx = t + i * 256;
        int s = idx >> 4, n = idx & 15;
        Bsh[s][n] = g_xBC[(size_t)(m0 + s) * CONV_DIM + D_INNER + n];
        Csh[s][n] = g_xBC[(size_t)(m0 + s) * CONV_DIM + D_INNER + D_STATE + n];
    }
    __syncthreads();
    #pragma unroll
    for (int i = 0; i < 16; i++) {
        int idx = t + i * 256;
        int s = idx >> 6, p = idx & 63;
        xs[s][p] = g_xBC[(size_t)(m0 + s) * CONV_DIM + h * HEADDIM + p] * dts[s];
    }
    __syncthreads();

    if (t == 0) {
        float Ah = -expf(A_log[h]);
        float run = 0.f;
        for (int s = 0; s < CHUNK; s++) { run += Ah * dts[s]; Acum[s] = run; }
    }
    __syncthreads();
    float Alast = Acum[CHUNK - 1];
    if (t < CHUNK) {
        decay[t] = expf(Alast - Acum[t]);
        g_Acum[(((size_t)(b * NCHUNK) + c) * NHEADS + h) * CHUNK + t] = Acum[t];
        r4[t] = (t < CHUNK - 4) ? expf(Acum[t + 4] - Acum[t]) : 0.f;
    }
    __syncthreads();

    // G[l][s] = (C[l]·B[s]) * exp(Acum[l]-Acum[s]), s <= l; exp via recurrence
    {
        const int s = t & 63;
        const int l0 = t >> 6;
        float4 Bq0 = *(const float4*)&Bsh[s][0];
        float4 Bq1 = *(const float4*)&Bsh[s][4];
        float4 Bq2 = *(const float4*)&Bsh[s][8];
        float4 Bq3 = *(const float4*)&Bsh[s][12];
        float As = Acum[s];
        float e = -1.f;
        #pragma unroll
        for (int i = 0; i < 16; i++) {
            int l = l0 + 4 * i;
            float g = 0.f;
            if (l >= s) {
                if (e < 0.f) e = expf(Acum[l] - As);
                else         e *= r4[l - 4];
                float4 c0 = *(const float4*)&Csh[l][0];
                float4 c1 = *(const float4*)&Csh[l][4];
                float4 c2 = *(const float4*)&Csh[l][8];
                float4 c3 = *(const float4*)&Csh[l][12];
                float d = c0.x * Bq0.x + c0.y * Bq0.y + c0.z * Bq0.z + c0.w * Bq0.w
                        + c1.x * Bq1.x + c1.y * Bq1.y + c1.z * Bq1.z + c1.w * Bq1.w
                        + c2.x * Bq2.x + c2.y * Bq2.y + c2.z * Bq2.z + c2.w * Bq2.w
                        + c3.x * Bq3.x + c3.y * Bq3.y + c3.z * Bq3.z + c3.w * Bq3.w;
                g = d * e;
            }
            Gs[l][s] = g;
        }
    }
    __syncthreads();

    // Y_diag = G @ x, s-unrolled by 4, all-float4 shared reads
    {
        const int p0 = (t & 15) * 4;
        const int l0 = (t >> 4) * 4;
        float acc[4][4];
        #pragma unroll
        for (int i = 0; i < 4; i++)
            #pragma unroll
            for (int j = 0; j < 4; j++) acc[i][j] = 0.f;
        for (int s0 = 0; s0 < CHUNK; s0 += 4) {
            float4 xq[4];
            #pragma unroll
            for (int j = 0; j < 4; j++) xq[j] = *(const float4*)&xs[s0 + j][p0];
            #pragma unroll
            for (int i = 0; i < 4; i++) {
                float4 gq = *(const float4*)&Gs[l0 + i][s0];
                acc[i][0] += gq.x * xq[0].x + gq.y * xq[1].x + gq.z * xq[2].x + gq.w * xq[3].x;
                acc[i][1] += gq.x * xq[0].y + gq.y * xq[1].y + gq.z * xq[2].y + gq.w * xq[3].y;
                acc[i][2] += gq.x * xq[0].z + gq.y * xq[1].z + gq.z * xq[2].z + gq.w * xq[3].z;
                acc[i][3] += gq.x * xq[0].w + gq.y * xq[1].w + gq.z * xq[2].w + gq.w * xq[3].w;
            }
        }
        #pragma unroll
        for (int i = 0; i < 4; i++)
            *(float4*)&g_y[(size_t)(m0 + l0 + i) * D_INNER + h * HEADDIM + p0] =
                make_float4(acc[i][0], acc[i][1], acc[i][2], acc[i][3]);
    }

    {
        const int p  = t & 63;
        const int nb = (t >> 6) * 4;
        float acc[4] = {0.f, 0.f, 0.f, 0.f};
        for (int s = 0; s < CHUNK; s++) {
            float xv = xs[s][p] * decay[s];
            #pragma unroll
            for (int j = 0; j < 4; j++) acc[j] += Bsh[s][nb + j] * xv;
        }
        size_t base = ((((size_t)(b * NCHUNK) + c) * NHEADS + h) * HEADDIM + p) * D_STATE + nb;
        #pragma unroll
        for (int j = 0; j < 4; j++) g_cs[base + j] = acc[j];
    }
}

// ---------------- SSD stage 2: sequential cross-chunk state scan ------------
__global__ __launch_bounds__(1024) void ssd_scan_kernel()
{
    const int bh = blockIdx.x;
    const int b = bh / NHEADS, h = bh % NHEADS;
    const int t = threadIdx.x;
    float state = 0.f;
    for (int c = 0; c < NCHUNK; c++) {
        size_t base = (((size_t)(b * NCHUNK) + c) * NHEADS + h) * (HEADDIM * D_STATE);
        g_sp[base + t] = state;
        float dA = expf(g_Acum[(((size_t)(b * NCHUNK) + c) * NHEADS + h) * CHUNK + (CHUNK - 1)]);
        state = state * dA + g_cs[base + t];
    }
}

// ---------------- SSD stage 3: off-diag + D*x + gate(silu(z)) ---------------
__global__ __launch_bounds__(256) void ssd_offdiag_kernel(const float* __restrict__ Dp)
{
    __shared__ float sp[CHUNK][D_STATE];
    __shared__ float Csh[CHUNK][D_STATE];
    __shared__ float eA[CHUNK];

    const int c = blockIdx.x, h = blockIdx.y, b = blockIdx.z;
    const int t = threadIdx.x;
    const int m0 = b * SEQ + c * CHUNK;
    size_t spbase = (((size_t)(b * NCHUNK) + c) * NHEADS + h) * (HEADDIM * D_STATE);

    #pragma unroll
    for (int i = 0; i < 4; i++) {
        int idx = t + i * 256;
        ((float*)sp)[idx] = g_sp[spbase + idx];
        int s = idx >> 4, n = idx & 15;
        Csh[s][n] = g_xBC[(size_t)(m0 + s) * CONV_DIM + D_INNER + D_STATE + n];
    }
    if (t < CHUNK)
        eA[t] = expf(g_Acum[(((size_t)(b * NCHUNK) + c) * NHEADS + h) * CHUNK + t]);
    __syncthreads();

    const float Dh = Dp[h];
    const int p = t & 63;
    const int lbase = (t >> 6) * 16;

    float spr[D_STATE];
    #pragma unroll
    for (int n = 0; n < D_STATE; n++) spr[n] = sp[p][n];

    for (int i = 0; i < 16; i++) {
        int l = lbase + i;
        int m = m0 + l;
        float d = 0.f;
        #pragma unroll
        for (int n = 0; n < D_STATE; n++) d += Csh[l][n] * spr[n];
        size_t yi = (size_t)m * D_INNER + h * HEADDIM + p;
        float yv = g_y[yi] + eA[l] * d;
        yv += Dh * g_xBC[(size_t)m * CONV_DIM + h * HEADDIM + p];
        float z = g_zxbcdt[(size_t)m * D_IN_PROJ + h * HEADDIM + p];
        yv *= z / (1.f + expf(-z));
        g_y[yi] = yv;
    }
}

// ---------------- RMSNorm over D_INNER + fp16 output ------------------------
__global__ __launch_bounds__(256) void rmsnorm_cvt_kernel(const float* __restrict__ norm_w)
{
    const int m = blockIdx.x;
    const int t = threadIdx.x;
    size_t base = (size_t)m * D_INNER;
    float s = 0.f;
    for (int i = t; i < D_INNER; i += 256) {
        float v = g_y[base + i];
        s += v * v;
    }
    __shared__ float red[256];
    red[t] = s; __syncthreads();
    for (int o = 128; o > 0; o >>= 1) {
        if (t < o) red[t] += red[t + o];
        __syncthreads();
    }
    float scale = rsqrtf(red[0] / (float)D_INNER + 1e-5f);
    for (int i = t; i < D_INNER; i += 256) {
        float v = g_y[base + i] * scale * norm_w[i];
        __half h = __float2half_rn(v);
        g_yh[base + i] = *(unsigned short*)&h;
    }
}

// ---------------- launch ----------------------------------------------------
extern "C" void kernel_launch(void* const* d_in, const int* in_sizes, int n_in,
                              void* d_out, int out_size)
{
    const float* u       = (const float*)d_in[0];
    const float* W_in    = (const float*)d_in[1];
    const float* conv_w  = (const float*)d_in[2];
    const float* conv_b  = (const float*)d_in[3];
    const float* dt_bias = (const float*)d_in[4];
    const float* A_log   = (const float*)d_in[5];
    const float* Dp      = (const float*)d_in[6];
    const float* norm_w  = (const float*)d_in[7];
    const float* W_out   = (const float*)d_in[8];
    float* out = (float*)d_out;

    float* zx;
    unsigned short *uh, *w1h, *yh, *w2h;
    cudaGetSymbolAddress((void**)&zx, g_zxbcdt);
    cudaGetSymbolAddress((void**)&uh, g_uh);
    cudaGetSymbolAddress((void**)&w1h, g_w1h);
    cudaGetSymbolAddress((void**)&yh, g_yh);
    cudaGetSymbolAddress((void**)&w2h, g_w2h);

    cudaFuncSetAttribute(f16gemm, cudaFuncAttributeMaxDynamicSharedMemorySize, GSMEM);

    // 0. convert inputs to fp16
    cvt16_kernel<<<(MTOT * D_MODEL) / 1024, 256>>>(u, uh, MTOT * D_MODEL);
    cvt16_kernel<<<(D_IN_PROJ * D_MODEL) / 1024, 256>>>(W_in, w1h, D_IN_PROJ * D_MODEL);
    cvt16_kernel<<<(D_MODEL * D_INNER) / 1024, 256>>>(W_out, w2h, D_MODEL * D_INNER);

    // 1. in_proj:  zxbcdt = u @ W_in^T   (8192 x 4160 x 1024)
    f16gemm<<<dim3((D_IN_PROJ + BN - 1) / BN, MTOT / BM), NTHR, GSMEM>>>(
        uh, w1h, zx, MTOT, D_IN_PROJ, D_MODEL);

    // 2. depthwise conv + silu on xBC slice, fused dt = softplus(raw + bias)
    conv_silu_dt_kernel<<<(MTOT * CONV_DIM + 255) / 256, 256>>>(conv_w, conv_b, dt_bias);

    // 3. SSD intra-chunk (Y_diag + chunk states)
    ssd_chunk_kernel<<<dim3(NCHUNK, NHEADS, BATCH), 256>>>(A_log);

    // 4. sequential cross-chunk scan
    ssd_scan_kernel<<<BATCH * NHEADS, 1024>>>();

    // 5. off-diagonal contribution + D*x + gating
    ssd_offdiag_kernel<<<dim3(NCHUNK, NHEADS, BATCH), 256>>>(Dp);

    // 6. RMSNorm (+ fp16 convert of y for out_proj)
    rmsnorm_cvt_kernel<<<MTOT, 256>>>(norm_w);

    // 7. out_proj: out = y @ W_out^T   (8192 x 1024 x 2048)
    f16gemm<<<dim3(D_MODEL / BN, MTOT / BM), NTHR, GSMEM>>>(
        yh, w2h, out, MTOT, D_MODEL, D_INNER);
}

// round 14
// speedup vs baseline: 2.0535x; 1.1209x over previous
#include <cuda_runtime.h>
#include <cuda_bf16.h>
#include <cuda_fp16.h>
#include <math.h>
#include <stdint.h>

#define D_MODEL   1024
#define D_STATE   16
#define D_CONV    4
#define HEADDIM   64
#define CHUNK     64
#define D_INNER   2048
#define NHEADS    32
#define CONV_DIM  2080          // D_INNER + 2*D_STATE
#define D_IN_PROJ 4160          // 2*D_INNER + 2*D_STATE + NHEADS
#define BATCH     2
#define SEQ       4096
#define NCHUNK    (SEQ / CHUNK) // 64
#define MTOT      (BATCH * SEQ) // 8192

// ---------------- scratch (device globals; no allocation allowed) -----------
__device__ float g_zxbcdt[(size_t)MTOT * D_IN_PROJ];
__device__ float g_xBC[(size_t)MTOT * CONV_DIM];
__device__ float g_dt[(size_t)MTOT * NHEADS];
__device__ float g_Acum[(size_t)BATCH * NCHUNK * NHEADS * CHUNK];
__device__ float g_cs[(size_t)BATCH * NCHUNK * NHEADS * HEADDIM * D_STATE];
__device__ float g_sp[(size_t)BATCH * NCHUNK * NHEADS * HEADDIM * D_STATE];
__device__ float g_y[(size_t)MTOT * D_INNER];

// fp16 buffers
__device__ unsigned short g_uh[(size_t)MTOT * D_MODEL];
__device__ unsigned short g_w1h[(size_t)D_IN_PROJ * D_MODEL];
__device__ unsigned short g_yh[(size_t)MTOT * D_INNER];
__device__ unsigned short g_w2h[(size_t)D_MODEL * D_INNER];

// ============================================================================
// helpers
// ============================================================================
__device__ __forceinline__ uint32_t cvta_s(const void* p) {
    uint32_t a;
    asm("{ .reg .u64 t; cvta.to.shared.u64 t, %1; cvt.u32.u64 %0, t; }" : "=r"(a) : "l"(p));
    return a;
}
__device__ __forceinline__ void cpa16(uint32_t dst, const void* src, int sz) {
    asm volatile("cp.async.cg.shared.global [%0], [%1], 16, %2;"
                 :: "r"(dst), "l"(src), "r"(sz));
}
#define CP_COMMIT() asm volatile("cp.async.commit_group;" ::: "memory")
#define CP_WAIT1()  asm volatile("cp.async.wait_group 1;" ::: "memory")

__device__ __forceinline__ void ldm_x4(uint32_t& r0, uint32_t& r1, uint32_t& r2,
                                       uint32_t& r3, uint32_t addr) {
    asm volatile("ldmatrix.sync.aligned.m8n8.x4.shared.b16 {%0,%1,%2,%3}, [%4];"
                 : "=r"(r0), "=r"(r1), "=r"(r2), "=r"(r3) : "r"(addr));
}
__device__ __forceinline__ void mma_f16(float* d, const uint32_t* a, const uint32_t* b) {
    asm volatile(
        "mma.sync.aligned.m16n8k16.row.col.f32.f16.f16.f32 "
        "{%0,%1,%2,%3},{%4,%5,%6,%7},{%8,%9},{%0,%1,%2,%3};"
        : "+f"(d[0]), "+f"(d[1]), "+f"(d[2]), "+f"(d[3])
        : "r"(a[0]), "r"(a[1]), "r"(a[2]), "r"(a[3]), "r"(b[0]), "r"(b[1]));
}

// ============================================================================
// fp16 GEMM (f32 accumulate): C[M,N] = A[M,K] @ B[N,K]^T
// CTA tile 128x128, BK=64, 128 threads (4 warps 2x2), warp tile 64x64,
// 3-stage cp.async pipeline, 2 CTAs/SM, cp.async spread across ks loop.
// ============================================================================
#define BM 128
#define BN 128
#define BKG 64
#define STG 3
#define NTHR 128
#define ATILE (BM * BKG * 2)       // 16384 B
#define BTILE (BN * BKG * 2)       // 16384 B
#define STGB (ATILE + BTILE)       // 32768 B
#define GSMEM (STG * STGB)         // 98304 B

__global__ __launch_bounds__(NTHR, 2) void f16gemm(
    const unsigned short* __restrict__ Ah,
    const unsigned short* __restrict__ Bh,
    float* __restrict__ C, int M, int N, int K)
{
    extern __shared__ char smraw[];
    const uint32_t smb = cvta_s(smraw);
    const int tid = threadIdx.x, lane = tid & 31, wid = tid >> 5;
    const int wm = (wid & 1) * 64, wn = (wid >> 1) * 64;
    const int qr = lane >> 2, qc = lane & 3;
    const int brow = blockIdx.y * BM, bcol = blockIdx.x * BN;
    const int KBt = K >> 6;

    float acc[4][8][4];
    #pragma unroll
    for (int mi = 0; mi < 4; mi++)
        #pragma unroll
        for (int ni = 0; ni < 8; ni++)
            #pragma unroll
            for (int r = 0; r < 4; r++) acc[mi][ni][r] = 0.f;

    auto issueA = [&](int kb) {
        if (kb >= KBt) return;
        const uint32_t abase = smb + (kb % STG) * STGB;
        #pragma unroll
        for (int p = 0; p < 8; p++) {
            int g = tid + p * NTHR;
            int r = g >> 3, cg = g & 7;
            cpa16(abase + r * 128 + ((cg ^ (r & 7)) * 16),
                  Ah + (size_t)(brow + r) * K + kb * BKG + cg * 8, 16);
        }
    };
    auto issueB = [&](int kb) {
        if (kb >= KBt) return;
        const uint32_t bbase = smb + (kb % STG) * STGB + ATILE;
        #pragma unroll
        for (int p = 0; p < 8; p++) {
            int g = tid + p * NTHR;
            int r = g >> 3, cg = g & 7;
            int bn = bcol + r;
            cpa16(bbase + r * 128 + ((cg ^ (r & 7)) * 16),
                  Bh + (size_t)(bn < N ? bn : 0) * K + kb * BKG + cg * 8,
                  bn < N ? 16 : 0);
        }
    };

    issueA(0); issueB(0); CP_COMMIT();
    issueA(1); issueB(1); CP_COMMIT();

    for (int kb = 0; kb < KBt; kb++) {
        CP_WAIT1();
        __syncthreads();

        const int st = kb % STG;
        const uint32_t abase = smb + st * STGB;
        const uint32_t bbase = abase + ATILE;
        #pragma unroll
        for (int ks = 0; ks < 4; ks++) {
            uint32_t af[4][4], bfr[8][2];
            #pragma unroll
            for (int mi = 0; mi < 4; mi++) {
                int r = wm + mi * 16 + (lane & 15);
                int g = (ks * 2 + (lane >> 4)) ^ (r & 7);
                ldm_x4(af[mi][0], af[mi][1], af[mi][2], af[mi][3],
                       abase + r * 128 + g * 16);
            }
            #pragma unroll
            for (int pi = 0; pi < 4; pi++) {
                int r = wn + pi * 16 + (lane & 7) + (((lane >> 4) & 1) << 3);
                int g = (ks * 2 + ((lane >> 3) & 1)) ^ (r & 7);
                ldm_x4(bfr[pi * 2][0], bfr[pi * 2][1],
                       bfr[pi * 2 + 1][0], bfr[pi * 2 + 1][1],
                       bbase + r * 128 + g * 16);
            }
            if (ks == 0) issueA(kb + 2);
            if (ks == 1) issueB(kb + 2);
            #pragma unroll
            for (int mi = 0; mi < 4; mi++)
                #pragma unroll
                for (int ni = 0; ni < 8; ni++)
                    mma_f16(acc[mi][ni], af[mi], bfr[ni]);
        }
        CP_COMMIT();
    }

    // epilogue
    #pragma unroll
    for (int mi = 0; mi < 4; mi++) {
        int row0 = brow + wm + mi * 16 + qr;
        #pragma unroll
        for (int ni = 0; ni < 8; ni++) {
            int col = bcol + wn + ni * 8 + qc * 2;
            if (col < N) {
                *(float2*)(C + (size_t)row0 * N + col) =
                    make_float2(acc[mi][ni][0], acc[mi][ni][1]);
                *(float2*)(C + (size_t)(row0 + 8) * N + col) =
                    make_float2(acc[mi][ni][2], acc[mi][ni][3]);
            }
        }
    }
}

// ---------------- fp32 -> fp16 conversion -----------------------------------
__global__ void cvt16_kernel(const float* __restrict__ s,
                             unsigned short* __restrict__ hi, int n)
{
    int i = (blockIdx.x * 256 + threadIdx.x) * 4;
    if (i >= n) return;
    float4 v = *(const float4*)(s + i);
    __half h0 = __float2half_rn(v.x);
    __half h1 = __float2half_rn(v.y);
    __half h2 = __float2half_rn(v.z);
    __half h3 = __float2half_rn(v.w);
    *(ushort4*)(hi + i) = make_ushort4(*(unsigned short*)&h0, *(unsigned short*)&h1,
                                       *(unsigned short*)&h2, *(unsigned short*)&h3);
}

// ---------------- depthwise causal conv(4) + bias + SiLU, fused dt ----------
// Each thread computes 4 consecutive tokens for one channel (7 loads / 4 outs).
__global__ void conv_silu_dt_kernel(const float* __restrict__ conv_w,
                                    const float* __restrict__ conv_b,
                                    const float* __restrict__ dt_bias)
{
    int idx = blockIdx.x * blockDim.x + threadIdx.x;

    if (idx < MTOT * NHEADS) {
        int h = idx & (NHEADS - 1);
        int m = idx >> 5;
        float x = g_zxbcdt[(size_t)m * D_IN_PROJ + (D_IN_PROJ - NHEADS) + h] + dt_bias[h];
        g_dt[idx] = (x > 20.f) ? x : log1pf(expf(x));
    }

    if (idx >= (MTOT / 4) * CONV_DIM) return;
    int c  = idx % CONV_DIM;
    int m0 = (idx / CONV_DIM) * 4;
    int l0 = m0 & (SEQ - 1);      // group never crosses a sequence boundary

    float w0 = conv_w[c * D_CONV + 0], w1 = conv_w[c * D_CONV + 1];
    float w2 = conv_w[c * D_CONV + 2], w3 = conv_w[c * D_CONV + 3];
    float bias = conv_b[c];

    float in[7];
    #pragma unroll
    for (int j = 0; j < 7; j++) {
        int off = j - 3;
        in[j] = (l0 + off >= 0)
              ? g_zxbcdt[(size_t)(m0 + off) * D_IN_PROJ + D_INNER + c] : 0.f;
    }
    #pragma unroll
    for (int i = 0; i < 4; i++) {
        float acc = bias + w0 * in[i] + w1 * in[i + 1] + w2 * in[i + 2] + w3 * in[i + 3];
        g_xBC[(size_t)(m0 + i) * CONV_DIM + c] = acc / (1.f + expf(-acc));
    }
}

// ---------------- SSD stage 1: per-chunk diag output + chunk states ---------
#define GPAD 4
__global__ __launch_bounds__(256) void ssd_chunk_kernel(const float* __restrict__ A_log)
{
    __shared__ float xs[CHUNK][HEADDIM];
    __shared__ float Gs[CHUNK][CHUNK + GPAD];   // padded: kills 16-way conflict
    __shared__ float Bsh[CHUNK][D_STATE];
    __shared__ float Csh[CHUNK][D_STATE];
    __shared__ float Acum[CHUNK];
    __shared__ float dts[CHUNK];
    __shared__ float decay[CHUNK];
    __shared__ float r4[CHUNK];          // r4[l] = exp(Acum[l+4]-Acum[l])

    const int c = blockIdx.x, h = blockIdx.y, b = blockIdx.z;
    const int t = threadIdx.x;
    const int m0 = b * SEQ + c * CHUNK;

    if (t < CHUNK) dts[t] = g_dt[(size_t)(m0 + t) * NHEADS + h];
    #pragma unroll
    for (int i = 0; i < 4; i++) {
        int idx = t + i * 256;
        int s = idx >> 4, n = idx & 15;
        Bsh[s][n] = g_xBC[(size_t)(m0 + s) * CONV_DIM + D_INNER + n];
        Csh[s][n] = g_xBC[(size_t)(m0 + s) * CONV_DIM + D_INNER + D_STATE + n];
    }
    __syncthreads();
    #pragma unroll
    for (int i = 0; i < 16; i++) {
        int idx = t + i * 256;
        int s = idx >> 6, p = idx & 63;
        xs[s][p] = g_xBC[(size_t)(m0 + s) * CONV_DIM + h * HEADDIM + p] * dts[s];
    }
    __syncthreads();

    if (t == 0) {
        float Ah = -expf(A_log[h]);
        float run = 0.f;
        for (int s = 0; s < CHUNK; s++) { run += Ah * dts[s]; Acum[s] = run; }
    }
    __syncthreads();
    float Alast = Acum[CHUNK - 1];
    if (t < CHUNK) {
        decay[t] = expf(Alast - Acum[t]);
        g_Acum[(((size_t)(b * NCHUNK) + c) * NHEADS + h) * CHUNK + t] = Acum[t];
        r4[t] = (t < CHUNK - 4) ? expf(Acum[t + 4] - Acum[t]) : 0.f;
    }
    __syncthreads();

    // G[l][s] = (C[l]·B[s]) * exp(Acum[l]-Acum[s]), s <= l; exp via recurrence
    {
        const int s = t & 63;
        const int l0 = t >> 6;
        float4 Bq0 = *(const float4*)&Bsh[s][0];
        float4 Bq1 = *(const float4*)&Bsh[s][4];
        float4 Bq2 = *(const float4*)&Bsh[s][8];
        float4 Bq3 = *(const float4*)&Bsh[s][12];
        float As = Acum[s];
        float e = -1.f;
        #pragma unroll
        for (int i = 0; i < 16; i++) {
            int l = l0 + 4 * i;
            float g = 0.f;
            if (l >= s) {
                if (e < 0.f) e = expf(Acum[l] - As);
                else         e *= r4[l - 4];
                float4 c0 = *(const float4*)&Csh[l][0];
                float4 c1 = *(const float4*)&Csh[l][4];
                float4 c2 = *(const float4*)&Csh[l][8];
                float4 c3 = *(const float4*)&Csh[l][12];
                float d = c0.x * Bq0.x + c0.y * Bq0.y + c0.z * Bq0.z + c0.w * Bq0.w
                        + c1.x * Bq1.x + c1.y * Bq1.y + c1.z * Bq1.z + c1.w * Bq1.w
                        + c2.x * Bq2.x + c2.y * Bq2.y + c2.z * Bq2.z + c2.w * Bq2.w
                        + c3.x * Bq3.x + c3.y * Bq3.y + c3.z * Bq3.z + c3.w * Bq3.w;
                g = d * e;
            }
            Gs[l][s] = g;
        }
    }
    __syncthreads();

    // Y_diag = G @ x, s-unrolled by 4, all-float4 shared reads
    {
        const int p0 = (t & 15) * 4;
        const int l0 = (t >> 4) * 4;
        float acc[4][4];
        #pragma unroll
        for (int i = 0; i < 4; i++)
            #pragma unroll
            for (int j = 0; j < 4; j++) acc[i][j] = 0.f;
        for (int s0 = 0; s0 < CHUNK; s0 += 4) {
            float4 xq[4];
            #pragma unroll
            for (int j = 0; j < 4; j++) xq[j] = *(const float4*)&xs[s0 + j][p0];
            #pragma unroll
            for (int i = 0; i < 4; i++) {
                float4 gq = *(const float4*)&Gs[l0 + i][s0];
                acc[i][0] += gq.x * xq[0].x + gq.y * xq[1].x + gq.z * xq[2].x + gq.w * xq[3].x;
                acc[i][1] += gq.x * xq[0].y + gq.y * xq[1].y + gq.z * xq[2].y + gq.w * xq[3].y;
                acc[i][2] += gq.x * xq[0].z + gq.y * xq[1].z + gq.z * xq[2].z + gq.w * xq[3].z;
                acc[i][3] += gq.x * xq[0].w + gq.y * xq[1].w + gq.z * xq[2].w + gq.w * xq[3].w;
            }
        }
        #pragma unroll
        for (int i = 0; i < 4; i++)
            *(float4*)&g_y[(size_t)(m0 + l0 + i) * D_INNER + h * HEADDIM + p0] =
                make_float4(acc[i][0], acc[i][1], acc[i][2], acc[i][3]);
    }

    {
        const int p  = t & 63;
        const int nb = (t >> 6) * 4;
        float acc[4] = {0.f, 0.f, 0.f, 0.f};
        for (int s = 0; s < CHUNK; s++) {
            float xv = xs[s][p] * decay[s];
            #pragma unroll
            for (int j = 0; j < 4; j++) acc[j] += Bsh[s][nb + j] * xv;
        }
        size_t base = ((((size_t)(b * NCHUNK) + c) * NHEADS + h) * HEADDIM + p) * D_STATE + nb;
        #pragma unroll
        for (int j = 0; j < 4; j++) g_cs[base + j] = acc[j];
    }
}

// ---------------- SSD stage 2: cross-chunk state scan (split elements) ------
#define SCAN_SPLIT 8
__global__ __launch_bounds__(128) void ssd_scan_kernel()
{
    const int blk = blockIdx.x;
    const int slice = blk & (SCAN_SPLIT - 1);
    const int bh = blk / SCAN_SPLIT;
    const int b = bh / NHEADS, h = bh % NHEADS;
    const int t = slice * 128 + threadIdx.x;    // element in [0, 1024)

    __shared__ float dAs[NCHUNK];
    if (threadIdx.x < NCHUNK) {
        int c = threadIdx.x;
        dAs[c] = expf(g_Acum[(((size_t)(b * NCHUNK) + c) * NHEADS + h) * CHUNK + (CHUNK - 1)]);
    }
    __syncthreads();

    float state = 0.f;
    #pragma unroll 4
    for (int c = 0; c < NCHUNK; c++) {
        size_t base = (((size_t)(b * NCHUNK) + c) * NHEADS + h) * (HEADDIM * D_STATE);
        float cs = g_cs[base + t];
        g_sp[base + t] = state;
        state = state * dAs[c] + cs;
    }
}

// ---------------- SSD stage 3: off-diag + D*x + gate(silu(z)) ---------------
__global__ __launch_bounds__(256) void ssd_offdiag_kernel(const float* __restrict__ Dp)
{
    __shared__ float sp[CHUNK][D_STATE];
    __shared__ float Csh[CHUNK][D_STATE];
    __shared__ float eA[CHUNK];

    const int c = blockIdx.x, h = blockIdx.y, b = blockIdx.z;
    const int t = threadIdx.x;
    const int m0 = b * SEQ + c * CHUNK;
    size_t spbase = (((size_t)(b * NCHUNK) + c) * NHEADS + h) * (HEADDIM * D_STATE);

    #pragma unroll
    for (int i = 0; i < 4; i++) {
        int idx = t + i * 256;
        ((float*)sp)[idx] = g_sp[spbase + idx];
        int s = idx >> 4, n = idx & 15;
        Csh[s][n] = g_xBC[(size_t)(m0 + s) * CONV_DIM + D_INNER + D_STATE + n];
    }
    if (t < CHUNK)
        eA[t] = expf(g_Acum[(((size_t)(b * NCHUNK) + c) * NHEADS + h) * CHUNK + t]);
    __syncthreads();

    const float Dh = Dp[h];
    const int p = t & 63;
    const int lbase = (t >> 6) * 16;

    float spr[D_STATE];
    #pragma unroll
    for (int n = 0; n < D_STATE; n++) spr[n] = sp[p][n];

    for (int i = 0; i < 16; i++) {
        int l = lbase + i;
        int m = m0 + l;
        float d = 0.f;
        #pragma unroll
        for (int n = 0; n < D_STATE; n++) d += Csh[l][n] * spr[n];
        size_t yi = (size_t)m * D_INNER + h * HEADDIM + p;
        float yv = g_y[yi] + eA[l] * d;
        yv += Dh * g_xBC[(size_t)m * CONV_DIM + h * HEADDIM + p];
        float z = g_zxbcdt[(size_t)m * D_IN_PROJ + h * HEADDIM + p];
        yv *= z / (1.f + expf(-z));
        g_y[yi] = yv;
    }
}

// ---------------- RMSNorm over D_INNER + fp16 output (register-cached) ------
__global__ __launch_bounds__(256) void rmsnorm_cvt_kernel(const float* __restrict__ norm_w)
{
    const int m = blockIdx.x;
    const int t = threadIdx.x;
    size_t base = (size_t)m * D_INNER;
    float vals[8];
    float s = 0.f;
    #pragma unroll
    for (int i = 0; i < 8; i++) {
        vals[i] = g_y[base + t + i * 256];
        s += vals[i] * vals[i];
    }
    __shared__ float red[256];
    red[t] = s; __syncthreads();
    for (int o = 128; o > 0; o >>= 1) {
        if (t < o) red[t] += red[t + o];
        __syncthreads();
    }
    float scale = rsqrtf(red[0] / (float)D_INNER + 1e-5f);
    #pragma unroll
    for (int i = 0; i < 8; i++) {
        float v = vals[i] * scale * norm_w[t + i * 256];
        __half h = __float2half_rn(v);
        g_yh[base + t + i * 256] = *(unsigned short*)&h;
    }
}

// ---------------- launch ----------------------------------------------------
extern "C" void kernel_launch(void* const* d_in, const int* in_sizes, int n_in,
                              void* d_out, int out_size)
{
    const float* u       = (const float*)d_in[0];
    const float* W_in    = (const float*)d_in[1];
    const float* conv_w  = (const float*)d_in[2];
    const float* conv_b  = (const float*)d_in[3];
    const float* dt_bias = (const float*)d_in[4];
    const float* A_log   = (const float*)d_in[5];
    const float* Dp      = (const float*)d_in[6];
    const float* norm_w  = (const float*)d_in[7];
    const float* W_out   = (const float*)d_in[8];
    float* out = (float*)d_out;

    float* zx;
    unsigned short *uh, *w1h, *yh, *w2h;
    cudaGetSymbolAddress((void**)&zx, g_zxbcdt);
    cudaGetSymbolAddress((void**)&uh, g_uh);
    cudaGetSymbolAddress((void**)&w1h, g_w1h);
    cudaGetSymbolAddress((void**)&yh, g_yh);
    cudaGetSymbolAddress((void**)&w2h, g_w2h);

    cudaFuncSetAttribute(f16gemm, cudaFuncAttributeMaxDynamicSharedMemorySize, GSMEM);

    // 0. convert inputs to fp16
    cvt16_kernel<<<(MTOT * D_MODEL) / 1024, 256>>>(u, uh, MTOT * D_MODEL);
    cvt16_kernel<<<(D_IN_PROJ * D_MODEL) / 1024, 256>>>(W_in, w1h, D_IN_PROJ * D_MODEL);
    cvt16_kernel<<<(D_MODEL * D_INNER) / 1024, 256>>>(W_out, w2h, D_MODEL * D_INNER);

    // 1. in_proj:  zxbcdt = u @ W_in^T   (8192 x 4160 x 1024)
    f16gemm<<<dim3((D_IN_PROJ + BN - 1) / BN, MTOT / BM), NTHR, GSMEM>>>(
        uh, w1h, zx, MTOT, D_IN_PROJ, D_MODEL);

    // 2. depthwise conv + silu (4 tokens/thread) + fused dt softplus
    conv_silu_dt_kernel<<<((MTOT / 4) * CONV_DIM + 255) / 256, 256>>>(conv_w, conv_b, dt_bias);

    // 3. SSD intra-chunk (Y_diag + chunk states)
    ssd_chunk_kernel<<<dim3(NCHUNK, NHEADS, BATCH), 256>>>(A_log);

    // 4. cross-chunk scan (element-split, 512 blocks)
    ssd_scan_kernel<<<BATCH * NHEADS * SCAN_SPLIT, 128>>>();

    // 5. off-diagonal contribution + D*x + gating
    ssd_offdiag_kernel<<<dim3(NCHUNK, NHEADS, BATCH), 256>>>(Dp);

    // 6. RMSNorm (+ fp16 convert of y for out_proj)
    rmsnorm_cvt_kernel<<<MTOT, 256>>>(norm_w);

    // 7. out_proj: out = y @ W_out^T   (8192 x 1024 x 2048)
    f16gemm<<<dim3(D_MODEL / BN, MTOT / BM), NTHR, GSMEM>>>(
        yh, w2h, out, MTOT, D_MODEL, D_INNER);
}

// round 15
// speedup vs baseline: 2.1008x; 1.0231x over previous
#include <cuda_runtime.h>
#include <cuda_bf16.h>
#include <cuda_fp16.h>
#include <math.h>
#include <stdint.h>

#define D_MODEL   1024
#define D_STATE   16
#define D_CONV    4
#define HEADDIM   64
#define CHUNK     64
#define D_INNER   2048
#define NHEADS    32
#define CONV_DIM  2080          // D_INNER + 2*D_STATE
#define D_IN_PROJ 4160          // 2*D_INNER + 2*D_STATE + NHEADS
#define BATCH     2
#define SEQ       4096
#define NCHUNK    (SEQ / CHUNK) // 64
#define MTOT      (BATCH * SEQ) // 8192

// ---------------- scratch (device globals; no allocation allowed) -----------
__device__ float g_zxbcdt[(size_t)MTOT * D_IN_PROJ];
__device__ float g_xBC[(size_t)MTOT * CONV_DIM];
__device__ float g_dt[(size_t)MTOT * NHEADS];
__device__ float g_Acum[(size_t)BATCH * NCHUNK * NHEADS * CHUNK];
__device__ float g_cs[(size_t)BATCH * NCHUNK * NHEADS * HEADDIM * D_STATE];
__device__ float g_sp[(size_t)BATCH * NCHUNK * NHEADS * HEADDIM * D_STATE];
__device__ float g_y[(size_t)MTOT * D_INNER];

// fp16 buffers
__device__ unsigned short g_uh[(size_t)MTOT * D_MODEL];
__device__ unsigned short g_w1h[(size_t)D_IN_PROJ * D_MODEL];
__device__ unsigned short g_yh[(size_t)MTOT * D_INNER];
__device__ unsigned short g_w2h[(size_t)D_MODEL * D_INNER];

// ============================================================================
// helpers
// ============================================================================
__device__ __forceinline__ uint32_t cvta_s(const void* p) {
    uint32_t a;
    asm("{ .reg .u64 t; cvta.to.shared.u64 t, %1; cvt.u32.u64 %0, t; }" : "=r"(a) : "l"(p));
    return a;
}
__device__ __forceinline__ void cpa16(uint32_t dst, const void* src, int sz) {
    asm volatile("cp.async.cg.shared.global [%0], [%1], 16, %2;"
                 :: "r"(dst), "l"(src), "r"(sz));
}
#define CP_COMMIT() asm volatile("cp.async.commit_group;" ::: "memory")
#define CP_WAIT1()  asm volatile("cp.async.wait_group 1;" ::: "memory")

__device__ __forceinline__ void ldm_x4(uint32_t& r0, uint32_t& r1, uint32_t& r2,
                                       uint32_t& r3, uint32_t addr) {
    asm volatile("ldmatrix.sync.aligned.m8n8.x4.shared.b16 {%0,%1,%2,%3}, [%4];"
                 : "=r"(r0), "=r"(r1), "=r"(r2), "=r"(r3) : "r"(addr));
}
__device__ __forceinline__ void mma_f16(float* d, const uint32_t* a, const uint32_t* b) {
    asm volatile(
        "mma.sync.aligned.m16n8k16.row.col.f32.f16.f16.f32 "
        "{%0,%1,%2,%3},{%4,%5,%6,%7},{%8,%9},{%0,%1,%2,%3};"
        : "+f"(d[0]), "+f"(d[1]), "+f"(d[2]), "+f"(d[3])
        : "r"(a[0]), "r"(a[1]), "r"(a[2]), "r"(a[3]), "r"(b[0]), "r"(b[1]));
}

// ============================================================================
// fp16 GEMM (f32 accumulate): C[M,N] = A[M,K] @ B[N,K]^T
// CTA tile 128x128, BK=64, 128 threads (4 warps 2x2), warp tile 64x64,
// 3-stage cp.async pipeline, 2 CTAs/SM, cp.async spread across ks loop.
// ============================================================================
#define BM 128
#define BN 128
#define BKG 64
#define STG 3
#define NTHR 128
#define ATILE (BM * BKG * 2)       // 16384 B
#define BTILE (BN * BKG * 2)       // 16384 B
#define STGB (ATILE + BTILE)       // 32768 B
#define GSMEM (STG * STGB)         // 98304 B

__global__ __launch_bounds__(NTHR, 2) void f16gemm(
    const unsigned short* __restrict__ Ah,
    const unsigned short* __restrict__ Bh,
    float* __restrict__ C, int M, int N, int K)
{
    extern __shared__ char smraw[];
    const uint32_t smb = cvta_s(smraw);
    const int tid = threadIdx.x, lane = tid & 31, wid = tid >> 5;
    const int wm = (wid & 1) * 64, wn = (wid >> 1) * 64;
    const int qr = lane >> 2, qc = lane & 3;
    const int brow = blockIdx.y * BM, bcol = blockIdx.x * BN;
    const int KBt = K >> 6;

    float acc[4][8][4];
    #pragma unroll
    for (int mi = 0; mi < 4; mi++)
        #pragma unroll
        for (int ni = 0; ni < 8; ni++)
            #pragma unroll
            for (int r = 0; r < 4; r++) acc[mi][ni][r] = 0.f;

    auto issueA = [&](int kb) {
        if (kb >= KBt) return;
        const uint32_t abase = smb + (kb % STG) * STGB;
        #pragma unroll
        for (int p = 0; p < 8; p++) {
            int g = tid + p * NTHR;
            int r = g >> 3, cg = g & 7;
            cpa16(abase + r * 128 + ((cg ^ (r & 7)) * 16),
                  Ah + (size_t)(brow + r) * K + kb * BKG + cg * 8, 16);
        }
    };
    auto issueB = [&](int kb) {
        if (kb >= KBt) return;
        const uint32_t bbase = smb + (kb % STG) * STGB + ATILE;
        #pragma unroll
        for (int p = 0; p < 8; p++) {
            int g = tid + p * NTHR;
            int r = g >> 3, cg = g & 7;
            int bn = bcol + r;
            cpa16(bbase + r * 128 + ((cg ^ (r & 7)) * 16),
                  Bh + (size_t)(bn < N ? bn : 0) * K + kb * BKG + cg * 8,
                  bn < N ? 16 : 0);
        }
    };

    issueA(0); issueB(0); CP_COMMIT();
    issueA(1); issueB(1); CP_COMMIT();

    for (int kb = 0; kb < KBt; kb++) {
        CP_WAIT1();
        __syncthreads();

        const int st = kb % STG;
        const uint32_t abase = smb + st * STGB;
        const uint32_t bbase = abase + ATILE;
        #pragma unroll
        for (int ks = 0; ks < 4; ks++) {
            uint32_t af[4][4], bfr[8][2];
            #pragma unroll
            for (int mi = 0; mi < 4; mi++) {
                int r = wm + mi * 16 + (lane & 15);
                int g = (ks * 2 + (lane >> 4)) ^ (r & 7);
                ldm_x4(af[mi][0], af[mi][1], af[mi][2], af[mi][3],
                       abase + r * 128 + g * 16);
            }
            #pragma unroll
            for (int pi = 0; pi < 4; pi++) {
                int r = wn + pi * 16 + (lane & 7) + (((lane >> 4) & 1) << 3);
                int g = (ks * 2 + ((lane >> 3) & 1)) ^ (r & 7);
                ldm_x4(bfr[pi * 2][0], bfr[pi * 2][1],
                       bfr[pi * 2 + 1][0], bfr[pi * 2 + 1][1],
                       bbase + r * 128 + g * 16);
            }
            if (ks == 0) issueA(kb + 2);
            if (ks == 1) issueB(kb + 2);
            #pragma unroll
            for (int mi = 0; mi < 4; mi++)
                #pragma unroll
                for (int ni = 0; ni < 8; ni++)
                    mma_f16(acc[mi][ni], af[mi], bfr[ni]);
        }
        CP_COMMIT();
    }

    // epilogue
    #pragma unroll
    for (int mi = 0; mi < 4; mi++) {
        int row0 = brow + wm + mi * 16 + qr;
        #pragma unroll
        for (int ni = 0; ni < 8; ni++) {
            int col = bcol + wn + ni * 8 + qc * 2;
            if (col < N) {
                *(float2*)(C + (size_t)row0 * N + col) =
                    make_float2(acc[mi][ni][0], acc[mi][ni][1]);
                *(float2*)(C + (size_t)(row0 + 8) * N + col) =
                    make_float2(acc[mi][ni][2], acc[mi][ni][3]);
            }
        }
    }
}

// ---------------- fp32 -> fp16 conversion -----------------------------------
__global__ void cvt16_kernel(const float* __restrict__ s,
                             unsigned short* __restrict__ hi, int n)
{
    int i = (blockIdx.x * 256 + threadIdx.x) * 4;
    if (i >= n) return;
    float4 v = *(const float4*)(s + i);
    __half h0 = __float2half_rn(v.x);
    __half h1 = __float2half_rn(v.y);
    __half h2 = __float2half_rn(v.z);
    __half h3 = __float2half_rn(v.w);
    *(ushort4*)(hi + i) = make_ushort4(*(unsigned short*)&h0, *(unsigned short*)&h1,
                                       *(unsigned short*)&h2, *(unsigned short*)&h3);
}

// ---------------- depthwise causal conv(4) + bias + SiLU, fused dt ----------
__global__ void conv_silu_dt_kernel(const float* __restrict__ conv_w,
                                    const float* __restrict__ conv_b,
                                    const float* __restrict__ dt_bias)
{
    int idx = blockIdx.x * blockDim.x + threadIdx.x;

    if (idx < MTOT * NHEADS) {
        int h = idx & (NHEADS - 1);
        int m = idx >> 5;
        float x = g_zxbcdt[(size_t)m * D_IN_PROJ + (D_IN_PROJ - NHEADS) + h] + dt_bias[h];
        g_dt[idx] = (x > 20.f) ? x : log1pf(expf(x));
    }

    if (idx >= (MTOT / 4) * CONV_DIM) return;
    int c  = idx % CONV_DIM;
    int m0 = (idx / CONV_DIM) * 4;
    int l0 = m0 & (SEQ - 1);

    float w0 = conv_w[c * D_CONV + 0], w1 = conv_w[c * D_CONV + 1];
    float w2 = conv_w[c * D_CONV + 2], w3 = conv_w[c * D_CONV + 3];
    float bias = conv_b[c];

    float in[7];
    #pragma unroll
    for (int j = 0; j < 7; j++) {
        int off = j - 3;
        in[j] = (l0 + off >= 0)
              ? g_zxbcdt[(size_t)(m0 + off) * D_IN_PROJ + D_INNER + c] : 0.f;
    }
    #pragma unroll
    for (int i = 0; i < 4; i++) {
        float acc = bias + w0 * in[i] + w1 * in[i + 1] + w2 * in[i + 2] + w3 * in[i + 3];
        g_xBC[(size_t)(m0 + i) * CONV_DIM + c] = acc / (1.f + __expf(-acc));
    }
}

// ---------------- SSD stage 1: per-chunk diag output + chunk states ---------
#define GPAD 4
__global__ __launch_bounds__(256) void ssd_chunk_kernel(const float* __restrict__ A_log)
{
    __shared__ float xs[CHUNK][HEADDIM];
    __shared__ float Gs[CHUNK][CHUNK + GPAD];
    __shared__ float Bsh[CHUNK][D_STATE];
    __shared__ float Csh[CHUNK][D_STATE];
    __shared__ float Acum[CHUNK];
    __shared__ float dts[CHUNK];
    __shared__ float decay[CHUNK];
    __shared__ float r4[CHUNK];

    const int c = blockIdx.x, h = blockIdx.y, b = blockIdx.z;
    const int t = threadIdx.x;
    const int m0 = b * SEQ + c * CHUNK;

    if (t < CHUNK) dts[t] = g_dt[(size_t)(m0 + t) * NHEADS + h];
    #pragma unroll
    for (int i = 0; i < 4; i++) {
        int idx = t + i * 256;
        int s = idx >> 4, n = idx & 15;
        Bsh[s][n] = g_xBC[(size_t)(m0 + s) * CONV_DIM + D_INNER + n];
        Csh[s][n] = g_xBC[(size_t)(m0 + s) * CONV_DIM + D_INNER + D_STATE + n];
    }
    __syncthreads();
    #pragma unroll
    for (int i = 0; i < 16; i++) {
        int idx = t + i * 256;
        int s = idx >> 6, p = idx & 63;
        xs[s][p] = g_xBC[(size_t)(m0 + s) * CONV_DIM + h * HEADDIM + p] * dts[s];
    }
    __syncthreads();

    if (t == 0) {
        float Ah = -expf(A_log[h]);
        float run = 0.f;
        for (int s = 0; s < CHUNK; s++) { run += Ah * dts[s]; Acum[s] = run; }
    }
    __syncthreads();
    float Alast = Acum[CHUNK - 1];
    if (t < CHUNK) {
        decay[t] = expf(Alast - Acum[t]);
        g_Acum[(((size_t)(b * NCHUNK) + c) * NHEADS + h) * CHUNK + t] = Acum[t];
        r4[t] = (t < CHUNK - 4) ? expf(Acum[t + 4] - Acum[t]) : 0.f;
    }
    __syncthreads();

    {
        const int s = t & 63;
        const int l0 = t >> 6;
        float4 Bq0 = *(const float4*)&Bsh[s][0];
        float4 Bq1 = *(const float4*)&Bsh[s][4];
        float4 Bq2 = *(const float4*)&Bsh[s][8];
        float4 Bq3 = *(const float4*)&Bsh[s][12];
        float As = Acum[s];
        float e = -1.f;
        #pragma unroll
        for (int i = 0; i < 16; i++) {
            int l = l0 + 4 * i;
            float g = 0.f;
            if (l >= s) {
                if (e < 0.f) e = expf(Acum[l] - As);
                else         e *= r4[l - 4];
                float4 c0 = *(const float4*)&Csh[l][0];
                float4 c1 = *(const float4*)&Csh[l][4];
                float4 c2 = *(const float4*)&Csh[l][8];
                float4 c3 = *(const float4*)&Csh[l][12];
                float d = c0.x * Bq0.x + c0.y * Bq0.y + c0.z * Bq0.z + c0.w * Bq0.w
                        + c1.x * Bq1.x + c1.y * Bq1.y + c1.z * Bq1.z + c1.w * Bq1.w
                        + c2.x * Bq2.x + c2.y * Bq2.y + c2.z * Bq2.z + c2.w * Bq2.w
                        + c3.x * Bq3.x + c3.y * Bq3.y + c3.z * Bq3.z + c3.w * Bq3.w;
                g = d * e;
            }
            Gs[l][s] = g;
        }
    }
    __syncthreads();

    {
        const int p0 = (t & 15) * 4;
        const int l0 = (t >> 4) * 4;
        float acc[4][4];
        #pragma unroll
        for (int i = 0; i < 4; i++)
            #pragma unroll
            for (int j = 0; j < 4; j++) acc[i][j] = 0.f;
        for (int s0 = 0; s0 < CHUNK; s0 += 4) {
            float4 xq[4];
            #pragma unroll
            for (int j = 0; j < 4; j++) xq[j] = *(const float4*)&xs[s0 + j][p0];
            #pragma unroll
            for (int i = 0; i < 4; i++) {
                float4 gq = *(const float4*)&Gs[l0 + i][s0];
                acc[i][0] += gq.x * xq[0].x + gq.y * xq[1].x + gq.z * xq[2].x + gq.w * xq[3].x;
                acc[i][1] += gq.x * xq[0].y + gq.y * xq[1].y + gq.z * xq[2].y + gq.w * xq[3].y;
                acc[i][2] += gq.x * xq[0].z + gq.y * xq[1].z + gq.z * xq[2].z + gq.w * xq[3].z;
                acc[i][3] += gq.x * xq[0].w + gq.y * xq[1].w + gq.z * xq[2].w + gq.w * xq[3].w;
            }
        }
        #pragma unroll
        for (int i = 0; i < 4; i++)
            *(float4*)&g_y[(size_t)(m0 + l0 + i) * D_INNER + h * HEADDIM + p0] =
                make_float4(acc[i][0], acc[i][1], acc[i][2], acc[i][3]);
    }

    {
        const int p  = t & 63;
        const int nb = (t >> 6) * 4;
        float acc[4] = {0.f, 0.f, 0.f, 0.f};
        for (int s = 0; s < CHUNK; s++) {
            float xv = xs[s][p] * decay[s];
            #pragma unroll
            for (int j = 0; j < 4; j++) acc[j] += Bsh[s][nb + j] * xv;
        }
        size_t base = ((((size_t)(b * NCHUNK) + c) * NHEADS + h) * HEADDIM + p) * D_STATE + nb;
        #pragma unroll
        for (int j = 0; j < 4; j++) g_cs[base + j] = acc[j];
    }
}

// ---------------- SSD stage 2: cross-chunk state scan (split elements) ------
#define SCAN_SPLIT 8
__global__ __launch_bounds__(128) void ssd_scan_kernel()
{
    const int blk = blockIdx.x;
    const int slice = blk & (SCAN_SPLIT - 1);
    const int bh = blk / SCAN_SPLIT;
    const int b = bh / NHEADS, h = bh % NHEADS;
    const int t = slice * 128 + threadIdx.x;

    __shared__ float dAs[NCHUNK];
    if (threadIdx.x < NCHUNK) {
        int c = threadIdx.x;
        dAs[c] = expf(g_Acum[(((size_t)(b * NCHUNK) + c) * NHEADS + h) * CHUNK + (CHUNK - 1)]);
    }
    __syncthreads();

    float state = 0.f;
    #pragma unroll 4
    for (int c = 0; c < NCHUNK; c++) {
        size_t base = (((size_t)(b * NCHUNK) + c) * NHEADS + h) * (HEADDIM * D_STATE);
        float cs = g_cs[base + t];
        g_sp[base + t] = state;
        state = state * dAs[c] + cs;
    }
}

// ---------------- Fused: off-diag + D*x + gate + RMSNorm + fp16 out ---------
// Grid (NCHUNK*2, BATCH), 512 threads. Block = 32 tokens x all 2048 channels.
// Thread owns 4 channels (ch = t + i*512); prefix-state rows in registers.
#define LTOK 32
__global__ __launch_bounds__(512) void ssd_off_norm_kernel(
    const float* __restrict__ Dp, const float* __restrict__ norm_w)
{
    __shared__ float Csh[LTOK][D_STATE];     // C rows (head-independent)
    __shared__ float eA[NHEADS][LTOK];
    __shared__ float Dsh[NHEADS];
    __shared__ float nw[D_INNER];
    __shared__ float warpsum[16];
    __shared__ float s_scale;

    const int bx = blockIdx.x;
    const int c = bx >> 1, half = bx & 1, b = blockIdx.y;
    const int l0 = half * LTOK;
    const int m0 = b * SEQ + c * CHUNK + l0;
    const int t = threadIdx.x;
    const int lane = t & 31, wrp = t >> 5;

    // C rows for these 32 tokens: 512 entries
    { int s = t >> 4, n = t & 15;
      Csh[s][n] = g_xBC[(size_t)(m0 + s) * CONV_DIM + D_INNER + D_STATE + n]; }
    // eA: 32 heads x 32 tokens = 1024 entries
    #pragma unroll
    for (int k = 0; k < 2; k++) {
        int idx = t + k * 512;
        int h = idx >> 5, l = idx & (LTOK - 1);
        eA[h][l] = __expf(g_Acum[(((size_t)(b * NCHUNK) + c) * NHEADS + h) * CHUNK + l0 + l]);
    }
    if (t < NHEADS) Dsh[t] = Dp[t];
    #pragma unroll
    for (int k = 0; k < 4; k++) nw[t + k * 512] = norm_w[t + k * 512];

    // prefix-state rows (independent of token within chunk)
    float spr[4][16];
    #pragma unroll
    for (int i = 0; i < 4; i++) {
        int ch = t + i * 512;
        int h = ch >> 6, p = ch & 63;
        const float4* sp4 = (const float4*)
            &g_sp[((((size_t)(b * NCHUNK) + c) * NHEADS + h) * HEADDIM + p) * D_STATE];
        #pragma unroll
        for (int q = 0; q < 4; q++) {
            float4 v = sp4[q];
            spr[i][q * 4 + 0] = v.x; spr[i][q * 4 + 1] = v.y;
            spr[i][q * 4 + 2] = v.z; spr[i][q * 4 + 3] = v.w;
        }
    }
    __syncthreads();

    float Dh[4], nwr[4];
    int hh[4];
    #pragma unroll
    for (int i = 0; i < 4; i++) {
        int ch = t + i * 512;
        hh[i] = ch >> 6;
        Dh[i] = Dsh[hh[i]];
        nwr[i] = nw[ch];
    }

    float ly[4], lx[4], lz[4];
    auto loadrow = [&](int l) {
        int m = m0 + l;
        #pragma unroll
        for (int i = 0; i < 4; i++) {
            int ch = t + i * 512;
            ly[i] = g_y[(size_t)m * D_INNER + ch];
            lx[i] = g_xBC[(size_t)m * CONV_DIM + ch];
            lz[i] = g_zxbcdt[(size_t)m * D_IN_PROJ + ch];
        }
    };
    loadrow(0);

    for (int l = 0; l < LTOK; l++) {
        float v[4];
        #pragma unroll
        for (int i = 0; i < 4; i++) {
            float d = 0.f;
            #pragma unroll
            for (int n = 0; n < D_STATE; n++) d += Csh[l][n] * spr[i][n];
            float yv = ly[i] + eA[hh[i]][l] * d + Dh[i] * lx[i];
            float z = lz[i];
            v[i] = yv * (z / (1.f + __expf(-z)));
        }
        int m = m0 + l;
        if (l + 1 < LTOK) loadrow(l + 1);   // overlap next loads with reduction

        float s = v[0] * v[0] + v[1] * v[1] + v[2] * v[2] + v[3] * v[3];
        #pragma unroll
        for (int o = 16; o > 0; o >>= 1) s += __shfl_xor_sync(~0u, s, o);
        if (lane == 0) warpsum[wrp] = s;
        __syncthreads();
        if (t < 16) {
            float w = warpsum[t];
            #pragma unroll
            for (int o = 8; o > 0; o >>= 1) w += __shfl_xor_sync(0xFFFF, w, o);
            if (t == 0) s_scale = rsqrtf(w / (float)D_INNER + 1e-5f);
        }
        __syncthreads();
        float sc = s_scale;
        #pragma unroll
        for (int i = 0; i < 4; i++) {
            __half hv = __float2half_rn(v[i] * sc * nwr[i]);
            g_yh[(size_t)m * D_INNER + t + i * 512] = *(unsigned short*)&hv;
        }
    }
}

// ---------------- launch ----------------------------------------------------
extern "C" void kernel_launch(void* const* d_in, const int* in_sizes, int n_in,
                              void* d_out, int out_size)
{
    const float* u       = (const float*)d_in[0];
    const float* W_in    = (const float*)d_in[1];
    const float* conv_w  = (const float*)d_in[2];
    const float* conv_b  = (const float*)d_in[3];
    const float* dt_bias = (const float*)d_in[4];
    const float* A_log   = (const float*)d_in[5];
    const float* Dp      = (const float*)d_in[6];
    const float* norm_w  = (const float*)d_in[7];
    const float* W_out   = (const float*)d_in[8];
    float* out = (float*)d_out;

    float* zx;
    unsigned short *uh, *w1h, *yh, *w2h;
    cudaGetSymbolAddress((void**)&zx, g_zxbcdt);
    cudaGetSymbolAddress((void**)&uh, g_uh);
    cudaGetSymbolAddress((void**)&w1h, g_w1h);
    cudaGetSymbolAddress((void**)&yh, g_yh);
    cudaGetSymbolAddress((void**)&w2h, g_w2h);

    cudaFuncSetAttribute(f16gemm, cudaFuncAttributeMaxDynamicSharedMemorySize, GSMEM);

    // 0. convert inputs to fp16
    cvt16_kernel<<<(MTOT * D_MODEL) / 1024, 256>>>(u, uh, MTOT * D_MODEL);
    cvt16_kernel<<<(D_IN_PROJ * D_MODEL) / 1024, 256>>>(W_in, w1h, D_IN_PROJ * D_MODEL);
    cvt16_kernel<<<(D_MODEL * D_INNER) / 1024, 256>>>(W_out, w2h, D_MODEL * D_INNER);

    // 1. in_proj:  zxbcdt = u @ W_in^T   (8192 x 4160 x 1024)
    f16gemm<<<dim3((D_IN_PROJ + BN - 1) / BN, MTOT / BM), NTHR, GSMEM>>>(
        uh, w1h, zx, MTOT, D_IN_PROJ, D_MODEL);

    // 2. depthwise conv + silu (4 tokens/thread) + fused dt softplus
    conv_silu_dt_kernel<<<((MTOT / 4) * CONV_DIM + 255) / 256, 256>>>(conv_w, conv_b, dt_bias);

    // 3. SSD intra-chunk (Y_diag + chunk states)
    ssd_chunk_kernel<<<dim3(NCHUNK, NHEADS, BATCH), 256>>>(A_log);

    // 4. cross-chunk scan (element-split, 512 blocks)
    ssd_scan_kernel<<<BATCH * NHEADS * SCAN_SPLIT, 128>>>();

    // 5. fused off-diag + gate + RMSNorm + fp16 convert
    ssd_off_norm_kernel<<<dim3(NCHUNK * 2, BATCH), 512>>>(Dp, norm_w);

    // 6. out_proj: out = y @ W_out^T   (8192 x 1024 x 2048)
    f16gemm<<<dim3(D_MODEL / BN, MTOT / BM), NTHR, GSMEM>>>(
        yh, w2h, out, MTOT, D_MODEL, D_INNER);
}

// round 17
// speedup vs baseline: 2.1600x; 1.0282x over previous
#include <cuda_runtime.h>
#include <cuda_bf16.h>
#include <cuda_fp16.h>
#include <math.h>
#include <stdint.h>

#define D_MODEL   1024
#define D_STATE   16
#define D_CONV    4
#define HEADDIM   64
#define CHUNK     64
#define D_INNER   2048
#define NHEADS    32
#define CONV_DIM  2080          // D_INNER + 2*D_STATE
#define D_IN_PROJ 4160          // 2*D_INNER + 2*D_STATE + NHEADS
#define BATCH     2
#define SEQ       4096
#define NCHUNK    (SEQ / CHUNK) // 64
#define MTOT      (BATCH * SEQ) // 8192

// ---------------- scratch (device globals; no allocation allowed) -----------
__device__ float g_zxbcdt[(size_t)MTOT * D_IN_PROJ];
__device__ float g_xBC[(size_t)MTOT * CONV_DIM];
__device__ float g_dt[(size_t)MTOT * NHEADS];
__device__ float g_Acum[(size_t)BATCH * NCHUNK * NHEADS * CHUNK];
__device__ float g_cs[(size_t)BATCH * NCHUNK * NHEADS * HEADDIM * D_STATE];
__device__ float g_sp[(size_t)BATCH * NCHUNK * NHEADS * HEADDIM * D_STATE];
__device__ float g_y[(size_t)MTOT * D_INNER];

// fp16 buffers
__device__ unsigned short g_uh[(size_t)MTOT * D_MODEL];
__device__ unsigned short g_w1h[(size_t)D_IN_PROJ * D_MODEL];
__device__ unsigned short g_yh[(size_t)MTOT * D_INNER];
__device__ unsigned short g_w2h[(size_t)D_MODEL * D_INNER];

// ============================================================================
// helpers
// ============================================================================
__device__ __forceinline__ uint32_t cvta_s(const void* p) {
    uint32_t a;
    asm("{ .reg .u64 t; cvta.to.shared.u64 t, %1; cvt.u32.u64 %0, t; }" : "=r"(a) : "l"(p));
    return a;
}
__device__ __forceinline__ void cpa16(uint32_t dst, const void* src, int sz) {
    asm volatile("cp.async.cg.shared.global [%0], [%1], 16, %2;"
                 :: "r"(dst), "l"(src), "r"(sz));
}
#define CP_COMMIT() asm volatile("cp.async.commit_group;" ::: "memory")
#define CP_WAIT1()  asm volatile("cp.async.wait_group 1;" ::: "memory")

__device__ __forceinline__ void ldm_x4(uint32_t& r0, uint32_t& r1, uint32_t& r2,
                                       uint32_t& r3, uint32_t addr) {
    asm volatile("ldmatrix.sync.aligned.m8n8.x4.shared.b16 {%0,%1,%2,%3}, [%4];"
                 : "=r"(r0), "=r"(r1), "=r"(r2), "=r"(r3) : "r"(addr));
}
__device__ __forceinline__ void mma_f16(float* d, const uint32_t* a, const uint32_t* b) {
    asm volatile(
        "mma.sync.aligned.m16n8k16.row.col.f32.f16.f16.f32 "
        "{%0,%1,%2,%3},{%4,%5,%6,%7},{%8,%9},{%0,%1,%2,%3};"
        : "+f"(d[0]), "+f"(d[1]), "+f"(d[2]), "+f"(d[3])
        : "r"(a[0]), "r"(a[1]), "r"(a[2]), "r"(a[3]), "r"(b[0]), "r"(b[1]));
}

// ============================================================================
// fp16 GEMM (f32 accumulate): C[M,N] = A[M,K] @ B[N,K]^T
// CTA tile 128x128, BK=64, 128 threads (4 warps 2x2), warp tile 64x64,
// 3-stage cp.async pipeline, 2 CTAs/SM, cp.async spread across ks loop.
// ============================================================================
#define BM 128
#define BN 128
#define BKG 64
#define STG 3
#define NTHR 128
#define ATILE (BM * BKG * 2)       // 16384 B
#define BTILE (BN * BKG * 2)       // 16384 B
#define STGB (ATILE + BTILE)       // 32768 B
#define GSMEM (STG * STGB)         // 98304 B

__global__ __launch_bounds__(NTHR, 2) void f16gemm(
    const unsigned short* __restrict__ Ah,
    const unsigned short* __restrict__ Bh,
    float* __restrict__ C, int M, int N, int K)
{
    extern __shared__ char smraw[];
    const uint32_t smb = cvta_s(smraw);
    const int tid = threadIdx.x, lane = tid & 31, wid = tid >> 5;
    const int wm = (wid & 1) * 64, wn = (wid >> 1) * 64;
    const int qr = lane >> 2, qc = lane & 3;
    const int brow = blockIdx.y * BM, bcol = blockIdx.x * BN;
    const int KBt = K >> 6;

    float acc[4][8][4];
    #pragma unroll
    for (int mi = 0; mi < 4; mi++)
        #pragma unroll
        for (int ni = 0; ni < 8; ni++)
            #pragma unroll
            for (int r = 0; r < 4; r++) acc[mi][ni][r] = 0.f;

    auto issueA = [&](int kb) {
        if (kb >= KBt) return;
        const uint32_t abase = smb + (kb % STG) * STGB;
        #pragma unroll
        for (int p = 0; p < 8; p++) {
            int g = tid + p * NTHR;
            int r = g >> 3, cg = g & 7;
            cpa16(abase + r * 128 + ((cg ^ (r & 7)) * 16),
                  Ah + (size_t)(brow + r) * K + kb * BKG + cg * 8, 16);
        }
    };
    auto issueB = [&](int kb) {
        if (kb >= KBt) return;
        const uint32_t bbase = smb + (kb % STG) * STGB + ATILE;
        #pragma unroll
        for (int p = 0; p < 8; p++) {
            int g = tid + p * NTHR;
            int r = g >> 3, cg = g & 7;
            int bn = bcol + r;
            cpa16(bbase + r * 128 + ((cg ^ (r & 7)) * 16),
                  Bh + (size_t)(bn < N ? bn : 0) * K + kb * BKG + cg * 8,
                  bn < N ? 16 : 0);
        }
    };

    issueA(0); issueB(0); CP_COMMIT();
    issueA(1); issueB(1); CP_COMMIT();

    for (int kb = 0; kb < KBt; kb++) {
        CP_WAIT1();
        __syncthreads();

        const int st = kb % STG;
        const uint32_t abase = smb + st * STGB;
        const uint32_t bbase = abase + ATILE;
        #pragma unroll
        for (int ks = 0; ks < 4; ks++) {
            uint32_t af[4][4], bfr[8][2];
            #pragma unroll
            for (int mi = 0; mi < 4; mi++) {
                int r = wm + mi * 16 + (lane & 15);
                int g = (ks * 2 + (lane >> 4)) ^ (r & 7);
                ldm_x4(af[mi][0], af[mi][1], af[mi][2], af[mi][3],
                       abase + r * 128 + g * 16);
            }
            #pragma unroll
            for (int pi = 0; pi < 4; pi++) {
                int r = wn + pi * 16 + (lane & 7) + (((lane >> 4) & 1) << 3);
                int g = (ks * 2 + ((lane >> 3) & 1)) ^ (r & 7);
                ldm_x4(bfr[pi * 2][0], bfr[pi * 2][1],
                       bfr[pi * 2 + 1][0], bfr[pi * 2 + 1][1],
                       bbase + r * 128 + g * 16);
            }
            if (ks == 0) issueA(kb + 2);
            if (ks == 1) issueB(kb + 2);
            #pragma unroll
            for (int mi = 0; mi < 4; mi++)
                #pragma unroll
                for (int ni = 0; ni < 8; ni++)
                    mma_f16(acc[mi][ni], af[mi], bfr[ni]);
        }
        CP_COMMIT();
    }

    // epilogue
    #pragma unroll
    for (int mi = 0; mi < 4; mi++) {
        int row0 = brow + wm + mi * 16 + qr;
        #pragma unroll
        for (int ni = 0; ni < 8; ni++) {
            int col = bcol + wn + ni * 8 + qc * 2;
            if (col < N) {
                *(float2*)(C + (size_t)row0 * N + col) =
                    make_float2(acc[mi][ni][0], acc[mi][ni][1]);
                *(float2*)(C + (size_t)(row0 + 8) * N + col) =
                    make_float2(acc[mi][ni][2], acc[mi][ni][3]);
            }
        }
    }
}

// ---------------- fp32 -> fp16 conversion -----------------------------------
__global__ void cvt16_kernel(const float* __restrict__ s,
                             unsigned short* __restrict__ hi, int n)
{
    int i = (blockIdx.x * 256 + threadIdx.x) * 4;
    if (i >= n) return;
    float4 v = *(const float4*)(s + i);
    __half h0 = __float2half_rn(v.x);
    __half h1 = __float2half_rn(v.y);
    __half h2 = __float2half_rn(v.z);
    __half h3 = __float2half_rn(v.w);
    *(ushort4*)(hi + i) = make_ushort4(*(unsigned short*)&h0, *(unsigned short*)&h1,
                                       *(unsigned short*)&h2, *(unsigned short*)&h3);
}

// ---------------- depthwise causal conv(4) + bias + SiLU, fused dt ----------
__global__ void conv_silu_dt_kernel(const float* __restrict__ conv_w,
                                    const float* __restrict__ conv_b,
                                    const float* __restrict__ dt_bias)
{
    int idx = blockIdx.x * blockDim.x + threadIdx.x;

    if (idx < MTOT * NHEADS) {
        int h = idx & (NHEADS - 1);
        int m = idx >> 5;
        float x = g_zxbcdt[(size_t)m * D_IN_PROJ + (D_IN_PROJ - NHEADS) + h] + dt_bias[h];
        g_dt[idx] = (x > 20.f) ? x : log1pf(expf(x));
    }

    if (idx >= (MTOT / 4) * CONV_DIM) return;
    int c  = idx % CONV_DIM;
    int m0 = (idx / CONV_DIM) * 4;
    int l0 = m0 & (SEQ - 1);

    float w0 = conv_w[c * D_CONV + 0], w1 = conv_w[c * D_CONV + 1];
    float w2 = conv_w[c * D_CONV + 2], w3 = conv_w[c * D_CONV + 3];
    float bias = conv_b[c];

    float in[7];
    #pragma unroll
    for (int j = 0; j < 7; j++) {
        int off = j - 3;
        in[j] = (l0 + off >= 0)
              ? g_zxbcdt[(size_t)(m0 + off) * D_IN_PROJ + D_INNER + c] : 0.f;
    }
    #pragma unroll
    for (int i = 0; i < 4; i++) {
        float acc = bias + w0 * in[i] + w1 * in[i + 1] + w2 * in[i + 2] + w3 * in[i + 3];
        g_xBC[(size_t)(m0 + i) * CONV_DIM + c] = acc / (1.f + __expf(-acc));
    }
}

// ---------------- SSD stage 1: per-chunk diag (fp16 MMA) + chunk states -----
// x stored fp16 transposed [p][s]; G split hi/lo fp16 [l][s].
// HLD=72 halves -> 144-byte rows: 16B-aligned for ldmatrix, and the 8 rows of
// each ldmatrix phase shift by 4 banks -> conflict-free.
#define HLD 72
__global__ __launch_bounds__(256) void ssd_chunk_kernel(const float* __restrict__ A_log)
{
    __shared__ __half xh[CHUNK][HLD];     // [p][s] = x[s][p]*dt[s]
    __shared__ __half Ghi[CHUNK][HLD];    // [l][s]
    __shared__ __half Glo[CHUNK][HLD];
    __shared__ float Bsh[CHUNK][D_STATE];
    __shared__ float Csh[CHUNK][D_STATE];
    __shared__ float Acum[CHUNK];
    __shared__ float dts[CHUNK];
    __shared__ float decay[CHUNK];
    __shared__ float r4[CHUNK];

    const int c = blockIdx.x, h = blockIdx.y, b = blockIdx.z;
    const int t = threadIdx.x;
    const int m0 = b * SEQ + c * CHUNK;
    const int lane = t & 31, w = t >> 5;

    if (t < CHUNK) dts[t] = g_dt[(size_t)(m0 + t) * NHEADS + h];
    #pragma unroll
    for (int i = 0; i < 4; i++) {
        int idx = t + i * 256;
        int s = idx >> 4, n = idx & 15;
        Bsh[s][n] = g_xBC[(size_t)(m0 + s) * CONV_DIM + D_INNER + n];
        Csh[s][n] = g_xBC[(size_t)(m0 + s) * CONV_DIM + D_INNER + D_STATE + n];
    }
    __syncthreads();
    #pragma unroll
    for (int i = 0; i < 16; i++) {
        int idx = t + i * 256;
        int s = idx >> 6, p = idx & 63;
        float v = g_xBC[(size_t)(m0 + s) * CONV_DIM + h * HEADDIM + p] * dts[s];
        xh[p][s] = __float2half_rn(v);
    }
    __syncthreads();

    if (t == 0) {
        float Ah = -expf(A_log[h]);
        float run = 0.f;
        for (int s = 0; s < CHUNK; s++) { run += Ah * dts[s]; Acum[s] = run; }
    }
    __syncthreads();
    float Alast = Acum[CHUNK - 1];
    if (t < CHUNK) {
        decay[t] = expf(Alast - Acum[t]);
        g_Acum[(((size_t)(b * NCHUNK) + c) * NHEADS + h) * CHUNK + t] = Acum[t];
        r4[t] = (t < CHUNK - 4) ? expf(Acum[t + 4] - Acum[t]) : 0.f;
    }
    __syncthreads();

    // G[l][s] = (C[l]·B[s]) * exp(Acum[l]-Acum[s]), s <= l; exp via recurrence;
    // store as fp16 hi/lo split (split exact to ~2^-22).
    {
        const int s = t & 63;
        const int l0 = t >> 6;
        float4 Bq0 = *(const float4*)&Bsh[s][0];
        float4 Bq1 = *(const float4*)&Bsh[s][4];
        float4 Bq2 = *(const float4*)&Bsh[s][8];
        float4 Bq3 = *(const float4*)&Bsh[s][12];
        float As = Acum[s];
        float e = -1.f;
        #pragma unroll
        for (int i = 0; i < 16; i++) {
            int l = l0 + 4 * i;
            float g = 0.f;
            if (l >= s) {
                if (e < 0.f) e = expf(Acum[l] - As);
                else         e *= r4[l - 4];
                float4 c0 = *(const float4*)&Csh[l][0];
                float4 c1 = *(const float4*)&Csh[l][4];
                float4 c2 = *(const float4*)&Csh[l][8];
                float4 c3 = *(const float4*)&Csh[l][12];
                float d = c0.x * Bq0.x + c0.y * Bq0.y + c0.z * Bq0.z + c0.w * Bq0.w
                        + c1.x * Bq1.x + c1.y * Bq1.y + c1.z * Bq1.z + c1.w * Bq1.w
                        + c2.x * Bq2.x + c2.y * Bq2.y + c2.z * Bq2.z + c2.w * Bq2.w
                        + c3.x * Bq3.x + c3.y * Bq3.y + c3.z * Bq3.z + c3.w * Bq3.w;
                g = d * e;
            }
            __half hi = __float2half_rn(g);
            Ghi[l][s] = hi;
            Glo[l][s] = __float2half_rn(g - __half2float(hi));
        }
    }
    __syncthreads();

    // Y_diag = (Ghi+Glo) @ x via fp16 MMA. 8 warps: mi = w&3 (16 l-rows),
    // nh = w>>2 (32 p-cols = 4 n8-tiles). K=64 in 4 k16 steps.
    {
        const uint32_t gb_hi = cvta_s(&Ghi[0][0]);
        const uint32_t gb_lo = cvta_s(&Glo[0][0]);
        const uint32_t xb    = cvta_s(&xh[0][0]);
        const int mi = w & 3, nh = w >> 2;
        const int qr = lane >> 2, qc = lane & 3;
        float acc[4][4];
        #pragma unroll
        for (int ni = 0; ni < 4; ni++)
            #pragma unroll
            for (int r = 0; r < 4; r++) acc[ni][r] = 0.f;

        #pragma unroll
        for (int ks = 0; ks < 4; ks++) {
            uint32_t ahi[4], alo[4], bfr[4][2];
            {
                int r = mi * 16 + (lane & 15);
                uint32_t off = (uint32_t)r * (HLD * 2) + (ks * 2 + (lane >> 4)) * 16;
                ldm_x4(ahi[0], ahi[1], ahi[2], ahi[3], gb_hi + off);
                ldm_x4(alo[0], alo[1], alo[2], alo[3], gb_lo + off);
            }
            #pragma unroll
            for (int pi = 0; pi < 2; pi++) {
                int r = nh * 32 + pi * 16 + (lane & 7) + (((lane >> 4) & 1) << 3);
                uint32_t off = (uint32_t)r * (HLD * 2) + (ks * 2 + ((lane >> 3) & 1)) * 16;
                ldm_x4(bfr[pi * 2][0], bfr[pi * 2][1],
                       bfr[pi * 2 + 1][0], bfr[pi * 2 + 1][1], xb + off);
            }
            #pragma unroll
            for (int ni = 0; ni < 4; ni++) {
                mma_f16(acc[ni], ahi, bfr[ni]);
                mma_f16(acc[ni], alo, bfr[ni]);
            }
        }
        int row0 = m0 + mi * 16 + qr;
        #pragma unroll
        for (int ni = 0; ni < 4; ni++) {
            int col = h * HEADDIM + nh * 32 + ni * 8 + qc * 2;
            *(float2*)(g_y + (size_t)row0 * D_INNER + col) =
                make_float2(acc[ni][0], acc[ni][1]);
            *(float2*)(g_y + (size_t)(row0 + 8) * D_INNER + col) =
                make_float2(acc[ni][2], acc[ni][3]);
        }
    }

    // chunk_states[p][n] = sum_s B[s,n] * decay[s] * x[s,p]  (x from fp16)
    {
        const int p  = t & 63;
        const int nb = (t >> 6) * 4;
        float acc[4] = {0.f, 0.f, 0.f, 0.f};
        for (int s = 0; s < CHUNK; s++) {
            float xv = __half2float(xh[p][s]) * decay[s];
            #pragma unroll
            for (int j = 0; j < 4; j++) acc[j] += Bsh[s][nb + j] * xv;
        }
        size_t base = ((((size_t)(b * NCHUNK) + c) * NHEADS + h) * HEADDIM + p) * D_STATE + nb;
        #pragma unroll
        for (int j = 0; j < 4; j++) g_cs[base + j] = acc[j];
    }
}

// ---------------- SSD stage 2: cross-chunk state scan (split elements) ------
#define SCAN_SPLIT 8
__global__ __launch_bounds__(128) void ssd_scan_kernel()
{
    const int blk = blockIdx.x;
    const int slice = blk & (SCAN_SPLIT - 1);
    const int bh = blk / SCAN_SPLIT;
    const int b = bh / NHEADS, h = bh % NHEADS;
    const int t = slice * 128 + threadIdx.x;

    __shared__ float dAs[NCHUNK];
    if (threadIdx.x < NCHUNK) {
        int c = threadIdx.x;
        dAs[c] = expf(g_Acum[(((size_t)(b * NCHUNK) + c) * NHEADS + h) * CHUNK + (CHUNK - 1)]);
    }
    __syncthreads();

    float state = 0.f;
    #pragma unroll 4
    for (int c = 0; c < NCHUNK; c++) {
        size_t base = (((size_t)(b * NCHUNK) + c) * NHEADS + h) * (HEADDIM * D_STATE);
        float cs = g_cs[base + t];
        g_sp[base + t] = state;
        state = state * dAs[c] + cs;
    }
}

// ---------------- Fused: off-diag + D*x + gate + RMSNorm + fp16 out ---------
#define LTOK 32
__global__ __launch_bounds__(512) void ssd_off_norm_kernel(
    const float* __restrict__ Dp, const float* __restrict__ norm_w)
{
    __shared__ float Csh[LTOK][D_STATE];
    __shared__ float eA[NHEADS][LTOK];
    __shared__ float Dsh[NHEADS];
    __shared__ float nw[D_INNER];
    __shared__ float warpsum[16];
    __shared__ float s_scale;

    const int bx = blockIdx.x;
    const int c = bx >> 1, half = bx & 1, b = blockIdx.y;
    const int l0 = half * LTOK;
    const int m0 = b * SEQ + c * CHUNK + l0;
    const int t = threadIdx.x;
    const int lane = t & 31, wrp = t >> 5;

    { int s = t >> 4, n = t & 15;
      Csh[s][n] = g_xBC[(size_t)(m0 + s) * CONV_DIM + D_INNER + D_STATE + n]; }
    #pragma unroll
    for (int k = 0; k < 2; k++) {
        int idx = t + k * 512;
        int h = idx >> 5, l = idx & (LTOK - 1);
        eA[h][l] = __expf(g_Acum[(((size_t)(b * NCHUNK) + c) * NHEADS + h) * CHUNK + l0 + l]);
    }
    if (t < NHEADS) Dsh[t] = Dp[t];
    #pragma unroll
    for (int k = 0; k < 4; k++) nw[t + k * 512] = norm_w[t + k * 512];

    float spr[4][16];
    #pragma unroll
    for (int i = 0; i < 4; i++) {
        int ch = t + i * 512;
        int h = ch >> 6, p = ch & 63;
        const float4* sp4 = (const float4*)
            &g_sp[((((size_t)(b * NCHUNK) + c) * NHEADS + h) * HEADDIM + p) * D_STATE];
        #pragma unroll
        for (int q = 0; q < 4; q++) {
            float4 v = sp4[q];
            spr[i][q * 4 + 0] = v.x; spr[i][q * 4 + 1] = v.y;
            spr[i][q * 4 + 2] = v.z; spr[i][q * 4 + 3] = v.w;
        }
    }
    __syncthreads();

    float Dh[4], nwr[4];
    int hh[4];
    #pragma unroll
    for (int i = 0; i < 4; i++) {
        int ch = t + i * 512;
        hh[i] = ch >> 6;
        Dh[i] = Dsh[hh[i]];
        nwr[i] = nw[ch];
    }

    float ly[4], lx[4], lz[4];
    auto loadrow = [&](int l) {
        int m = m0 + l;
        #pragma unroll
        for (int i = 0; i < 4; i++) {
            int ch = t + i * 512;
            ly[i] = g_y[(size_t)m * D_INNER + ch];
            lx[i] = g_xBC[(size_t)m * CONV_DIM + ch];
            lz[i] = g_zxbcdt[(size_t)m * D_IN_PROJ + ch];
        }
    };
    loadrow(0);

    for (int l = 0; l < LTOK; l++) {
        float v[4];
        #pragma unroll
        for (int i = 0; i < 4; i++) {
            float d = 0.f;
            #pragma unroll
            for (int n = 0; n < D_STATE; n++) d += Csh[l][n] * spr[i][n];
            float yv = ly[i] + eA[hh[i]][l] * d + Dh[i] * lx[i];
            float z = lz[i];
            v[i] = yv * (z / (1.f + __expf(-z)));
        }
        int m = m0 + l;
        if (l + 1 < LTOK) loadrow(l + 1);

        float s = v[0] * v[0] + v[1] * v[1] + v[2] * v[2] + v[3] * v[3];
        #pragma unroll
        for (int o = 16; o > 0; o >>= 1) s += __shfl_xor_sync(~0u, s, o);
        if (lane == 0) warpsum[wrp] = s;
        __syncthreads();
        if (t < 16) {
            float w = warpsum[t];
            #pragma unroll
            for (int o = 8; o > 0; o >>= 1) w += __shfl_xor_sync(0xFFFF, w, o);
            if (t == 0) s_scale = rsqrtf(w / (float)D_INNER + 1e-5f);
        }
        __syncthreads();
        float sc = s_scale;
        #pragma unroll
        for (int i = 0; i < 4; i++) {
            __half hv = __float2half_rn(v[i] * sc * nwr[i]);
            g_yh[(size_t)m * D_INNER + t + i * 512] = *(unsigned short*)&hv;
        }
    }
}

// ---------------- launch ----------------------------------------------------
extern "C" void kernel_launch(void* const* d_in, const int* in_sizes, int n_in,
                              void* d_out, int out_size)
{
    const float* u       = (const float*)d_in[0];
    const float* W_in    = (const float*)d_in[1];
    const float* conv_w  = (const float*)d_in[2];
    const float* conv_b  = (const float*)d_in[3];
    const float* dt_bias = (const float*)d_in[4];
    const float* A_log   = (const float*)d_in[5];
    const float* Dp      = (const float*)d_in[6];
    const float* norm_w  = (const float*)d_in[7];
    const float* W_out   = (const float*)d_in[8];
    float* out = (float*)d_out;

    float* zx;
    unsigned short *uh, *w1h, *yh, *w2h;
    cudaGetSymbolAddress((void**)&zx, g_zxbcdt);
    cudaGetSymbolAddress((void**)&uh, g_uh);
    cudaGetSymbolAddress((void**)&w1h, g_w1h);
    cudaGetSymbolAddress((void**)&yh, g_yh);
    cudaGetSymbolAddress((void**)&w2h, g_w2h);

    cudaFuncSetAttribute(f16gemm, cudaFuncAttributeMaxDynamicSharedMemorySize, GSMEM);

    // 0. convert inputs to fp16
    cvt16_kernel<<<(MTOT * D_MODEL) / 1024, 256>>>(u, uh, MTOT * D_MODEL);
    cvt16_kernel<<<(D_IN_PROJ * D_MODEL) / 1024, 256>>>(W_in, w1h, D_IN_PROJ * D_MODEL);
    cvt16_kernel<<<(D_MODEL * D_INNER) / 1024, 256>>>(W_out, w2h, D_MODEL * D_INNER);

    // 1. in_proj:  zxbcdt = u @ W_in^T   (8192 x 4160 x 1024)
    f16gemm<<<dim3((D_IN_PROJ + BN - 1) / BN, MTOT / BM), NTHR, GSMEM>>>(
        uh, w1h, zx, MTOT, D_IN_PROJ, D_MODEL);

    // 2. depthwise conv + silu (4 tokens/thread) + fused dt softplus
    conv_silu_dt_kernel<<<((MTOT / 4) * CONV_DIM + 255) / 256, 256>>>(conv_w, conv_b, dt_bias);

    // 3. SSD intra-chunk (Y_diag via fp16 MMA + chunk states)
    ssd_chunk_kernel<<<dim3(NCHUNK, NHEADS, BATCH), 256>>>(A_log);

    // 4. cross-chunk scan (element-split, 512 blocks)
    ssd_scan_kernel<<<BATCH * NHEADS * SCAN_SPLIT, 128>>>();

    // 5. fused off-diag + gate + RMSNorm + fp16 convert
    ssd_off_norm_kernel<<<dim3(NCHUNK * 2, BATCH), 512>>>(Dp, norm_w);

    // 6. out_proj: out = y @ W_out^T   (8192 x 1024 x 2048)
    f16gemm<<<dim3(D_MODEL / BN, MTOT / BM), NTHR, GSMEM>>>(
        yh, w2h, out, MTOT, D_MODEL, D_INNER);
}